// round 8
// baseline (speedup 1.0000x reference)
#include <cuda_runtime.h>
#include <cuda_bf16.h>
#include <cstdint>

#define BNUM   4
#define SEQ    512
#define DMODEL 1024
#define HDIM   256
#define MTOT   2048
#define KP1    3072      // 3 * DMODEL (hi|lo|hi concat)
#define KP2    768       // 3 * HDIM
#define NJC    1024      // SEQ * 2 (j,c interleaved)
#define NSPLIT 8         // split-K factor for stage-1 GEMM
#define KSPL   (KP1 / NSPLIT)   // 384

// Scratch (allocation-free __device__ globals)
__device__ __align__(16) float         g_p1[NSPLIT * MTOT * HDIM];  // 16 MB partials
__device__ __align__(16) __nv_bfloat16 g_Xp[MTOT * KP1];            // 12 MB
__device__ __align__(16) __nv_bfloat16 g_W1p[HDIM * KP1];           // 1.5 MB
__device__ __align__(16) __nv_bfloat16 g_Ap[MTOT * KP2];            // 3 MB
__device__ __align__(16) __nv_bfloat16 g_Bp[BNUM * NJC * KP2];      // 6 MB

// ---------------------------------------------------------------------------
// helpers
// ---------------------------------------------------------------------------
static __device__ __forceinline__ uint32_t smem_u32(const void* p) {
    uint32_t a;
    asm("{ .reg .u64 t; cvta.to.shared.u64 t, %1; cvt.u32.u64 %0, t; }"
        : "=r"(a) : "l"(p));
    return a;
}
static __device__ __forceinline__ void cp_async16(uint32_t saddr, const void* gaddr) {
    asm volatile("cp.async.cg.shared.global [%0], [%1], 16;"
                 :: "r"(saddr), "l"(gaddr) : "memory");
}
static __device__ __forceinline__ void cp_commit() {
    asm volatile("cp.async.commit_group;" ::: "memory");
}
static __device__ __forceinline__ void cp_wait2() {
    asm volatile("cp.async.wait_group 2;" ::: "memory");
}
static __device__ __forceinline__ void cp_wait0() {
    asm volatile("cp.async.wait_group 0;" ::: "memory");
}
static __device__ __forceinline__ void ldsm_x4(uint32_t* r, uint32_t addr) {
    asm volatile("ldmatrix.sync.aligned.m8n8.x4.shared.b16 {%0,%1,%2,%3}, [%4];"
                 : "=r"(r[0]), "=r"(r[1]), "=r"(r[2]), "=r"(r[3]) : "r"(addr));
}
static __device__ __forceinline__ void mma16816(float* d, const uint32_t* a,
                                                uint32_t b0, uint32_t b1) {
    asm volatile(
        "mma.sync.aligned.m16n8k16.row.col.f32.bf16.bf16.f32 "
        "{%0,%1,%2,%3}, {%4,%5,%6,%7}, {%8,%9}, {%0,%1,%2,%3};"
        : "+f"(d[0]), "+f"(d[1]), "+f"(d[2]), "+f"(d[3])
        : "r"(a[0]), "r"(a[1]), "r"(a[2]), "r"(a[3]), "r"(b0), "r"(b1));
}
static __device__ __forceinline__ void st_bf2(__nv_bfloat16* p, __nv_bfloat16 a, __nv_bfloat16 b) {
    __nv_bfloat162 t; t.x = a; t.y = b;
    *(__nv_bfloat162*)p = t;
}
static __device__ __forceinline__ void split1(float v, __nv_bfloat16& h, __nv_bfloat16& l) {
    h = __float2bfloat16_rn(v);
    l = __float2bfloat16_rn(v - __bfloat162float(h));
}

// ---------------------------------------------------------------------------
// Prep 1: split X -> [hi|lo|hi], W1 -> [hi|hi|lo]
// ---------------------------------------------------------------------------
__global__ __launch_bounds__(256) void split_xw(const float* __restrict__ X,
                                                const float* __restrict__ W1) {
    const int NX4 = MTOT * DMODEL / 4;   // 524288
    int idx = blockIdx.x * 256 + threadIdx.x;
    if (idx < NX4) {
        int r = idx >> 8;
        int k = (idx & 255) * 4;
        float4 v = *(const float4*)(X + (size_t)r * DMODEL + k);
        __nv_bfloat16 h0,h1,h2,h3,l0,l1,l2,l3;
        split1(v.x,h0,l0); split1(v.y,h1,l1); split1(v.z,h2,l2); split1(v.w,h3,l3);
        __nv_bfloat16* base = g_Xp + (size_t)r * KP1 + k;
        st_bf2(base,              h0,h1); st_bf2(base+2,              h2,h3);
        st_bf2(base+DMODEL,       l0,l1); st_bf2(base+DMODEL+2,       l2,l3);
        st_bf2(base+2*DMODEL,     h0,h1); st_bf2(base+2*DMODEL+2,     h2,h3);
    } else {
        int i2 = idx - NX4;
        if (i2 >= HDIM * DMODEL / 4) return;
        int r = i2 >> 8;
        int k = (i2 & 255) * 4;
        float4 v = *(const float4*)(W1 + (size_t)r * DMODEL + k);
        __nv_bfloat16 h0,h1,h2,h3,l0,l1,l2,l3;
        split1(v.x,h0,l0); split1(v.y,h1,l1); split1(v.z,h2,l2); split1(v.w,h3,l3);
        __nv_bfloat16* base = g_W1p + (size_t)r * KP1 + k;
        st_bf2(base,              h0,h1); st_bf2(base+2,              h2,h3);
        st_bf2(base+DMODEL,       h0,h1); st_bf2(base+DMODEL+2,       h2,h3);
        st_bf2(base+2*DMODEL,     l0,l1); st_bf2(base+2*DMODEL+2,     l2,l3);
    }
}

// ---------------------------------------------------------------------------
// Prep 2 (fused reduce): o = sum_s p1[s] + b1; A' = [o_hi|o_lo|o_hi];
// B' rows jc=2j+c: v=o*w_c, [v_hi|v_hi|v_lo]
// ---------------------------------------------------------------------------
__global__ __launch_bounds__(256) void prep_o(const float* __restrict__ W2,
                                              const float* __restrict__ b1) {
    int idx = blockIdx.x * 256 + threadIdx.x;       // over 2048*64
    int m = idx >> 6;
    int h = (idx & 63) * 4;

    float4 o4 = *(const float4*)(g_p1 + (size_t)m * HDIM + h);
#pragma unroll
    for (int s = 1; s < NSPLIT; ++s) {
        float4 p = *(const float4*)(g_p1 + ((size_t)s * MTOT + m) * HDIM + h);
        o4.x += p.x; o4.y += p.y; o4.z += p.z; o4.w += p.w;
    }
    float4 bb = *(const float4*)(b1 + h);
    o4.x += bb.x; o4.y += bb.y; o4.z += bb.z; o4.w += bb.w;

    __nv_bfloat16 h0,h1,h2,h3,l0,l1,l2,l3;
    split1(o4.x,h0,l0); split1(o4.y,h1,l1); split1(o4.z,h2,l2); split1(o4.w,h3,l3);
    __nv_bfloat16* abase = g_Ap + (size_t)m * KP2 + h;
    st_bf2(abase,          h0,h1); st_bf2(abase+2,          h2,h3);
    st_bf2(abase+HDIM,     l0,l1); st_bf2(abase+HDIM+2,     l2,l3);
    st_bf2(abase+2*HDIM,   h0,h1); st_bf2(abase+2*HDIM+2,   h2,h3);

    int b = m >> 9, j = m & 511;
    float4 w0 = *(const float4*)(W2 + h);
    float4 w1 = *(const float4*)(W2 + HDIM + h);
#pragma unroll
    for (int c = 0; c < 2; ++c) {
        float4 w = c ? w1 : w0;
        float4 v;
        v.x = o4.x * w.x; v.y = o4.y * w.y; v.z = o4.z * w.z; v.w = o4.w * w.w;
        __nv_bfloat16 vh0,vh1,vh2,vh3,vl0,vl1,vl2,vl3;
        split1(v.x,vh0,vl0); split1(v.y,vh1,vl1); split1(v.z,vh2,vl2); split1(v.w,vh3,vl3);
        __nv_bfloat16* bbase = g_Bp + ((size_t)b * NJC + 2 * j + c) * KP2 + h;
        st_bf2(bbase,          vh0,vh1); st_bf2(bbase+2,          vh2,vh3);
        st_bf2(bbase+HDIM,     vh0,vh1); st_bf2(bbase+HDIM+2,     vh2,vh3);
        st_bf2(bbase+2*HDIM,   vl0,vl1); st_bf2(bbase+2*HDIM+2,   vl2,vl3);
    }
}

// ---------------------------------------------------------------------------
// mma.sync bf16 TN GEMM: CTA tile 64(M) x 128(N), BK=32, 4-stage cp.async
// pipeline, 256 threads / 8 warps = 2M x 2N x 2(k16-group). Warp tile 32x64.
// Stage block (12KB): A 64x64B at +0, B 128x64B at +4096.
// XOR swizzle: 16B chunk ^= (row>>1)&3.
// mode 0: C = g_p1[z]; grid (2, 32, 8); k-window z*KSPL, NC=12.
// mode 1: C = out, triangular grid (36, 1, 4): block pair (it<=jt) of 64-row
//         i-tile x 64-j tile (128 jc cols); off-diagonal tiles also store the
//         mirrored tile out[b,j,i,c] via smem transpose. NC=24.
// ---------------------------------------------------------------------------
#define BK   32
#define STB  12288                    // stage bytes: A 4KB + B 8KB
#define NSTG 4
#define SMEM_SZ (NSTG * STB)          // 49152 == default 48KB limit
#define SDP  132                      // fp32 combine-tile pitch

__global__ __launch_bounds__(256, 2) void gemm_kernel(int mode,
                                                      const float* __restrict__ bias,
                                                      float* __restrict__ outp) {
    extern __shared__ char smem[];
    const uint32_t sbase = smem_u32(smem);
    const int tid = threadIdx.x;
    const int wid = tid >> 5, lane = tid & 31;
    const int grp = wid >> 2;                        // k16 group 0/1
    const int wm = wid & 1, wn = (wid >> 1) & 1;     // 2x2 warp grid per group
    const int bz = blockIdx.z;

    int m0, it = 0, jt = 0, nt = 0;
    const __nv_bfloat16* Ab;
    const __nv_bfloat16* Bb;
    int KpA, KpB, nc;
    if (mode == 0) {
        nt = blockIdx.x; it = blockIdx.y;
        m0 = it * 64;
        Ab = g_Xp + (size_t)m0 * KP1 + bz * KSPL;
        Bb = g_W1p + (size_t)(nt * 128) * KP1 + bz * KSPL;
        KpA = KP1; KpB = KP1; nc = KSPL / BK;        // 12
    } else {
        int idx = blockIdx.x;                        // 0..35, idx = jt(jt+1)/2 + it
        jt = (int)((__fsqrt_rn(8.0f * idx + 1.0f) - 1.0f) * 0.5f);
        while (((jt + 1) * (jt + 2) >> 1) <= idx) ++jt;
        while (((jt * (jt + 1)) >> 1) > idx) --jt;
        it = idx - ((jt * (jt + 1)) >> 1);
        m0 = it * 64;
        Ab = g_Ap + ((size_t)(bz * SEQ + m0)) * KP2;
        Bb = g_Bp + ((size_t)(bz * NJC + jt * 128)) * KP2;
        KpA = KP2; KpB = KP2; nc = KP2 / BK;         // 24
    }

    // cp.async mapping: lrow = tid>>2 (0..63), lc = tid&3 (16B chunk)
    const int lrow = tid >> 2;
    const int lc   = tid & 3;
    const uint32_t swl  = (uint32_t)((lc ^ ((lrow >> 1) & 3)) << 4);
    const uint32_t aSt  = (uint32_t)(lrow * 64) + swl;                // A row lrow
    const uint32_t bSt0 = 4096u + (uint32_t)(lrow * 64) + swl;        // B row lrow
    const uint32_t bSt1 = 4096u + (uint32_t)((64 + lrow) * 64) + swl; // B row 64+lrow (same key)

    float acc[2][8][4];
#pragma unroll
    for (int mt = 0; mt < 2; ++mt)
#pragma unroll
        for (int j = 0; j < 8; ++j)
#pragma unroll
            for (int e = 0; e < 4; ++e) acc[mt][j][e] = 0.0f;

    // prologue: stages 0..2
#pragma unroll
    for (int s = 0; s < 3; ++s) {
        const __nv_bfloat16* Ag  = Ab + s * BK + (size_t)lrow * KpA + lc * 8;
        const __nv_bfloat16* Bg0 = Bb + s * BK + (size_t)lrow * KpB + lc * 8;
        const __nv_bfloat16* Bg1 = Bb + s * BK + (size_t)(64 + lrow) * KpB + lc * 8;
        const uint32_t st = sbase + s * STB;
        cp_async16(st + aSt,  Ag);
        cp_async16(st + bSt0, Bg0);
        cp_async16(st + bSt1, Bg1);
        cp_commit();
    }

    // ldmatrix bases; rows +16/+32/+48 share the same xor key
    const int arow = wm * 32 + (lane & 15);
    const int brow = wn * 64 + (lane & 15);
    const int kl   = lane >> 4;
    const int c16  = grp * 2 + kl;
    const uint32_t aOff = (uint32_t)(arow * 64) + (uint32_t)((c16 ^ ((arow >> 1) & 3)) << 4);
    const uint32_t bOff = 4096u + (uint32_t)(brow * 64) + (uint32_t)((c16 ^ ((brow >> 1) & 3)) << 4);

    for (int kc = 0; kc < nc; ++kc) {
        cp_wait2();
        __syncthreads();

        const uint32_t stg = sbase + (uint32_t)((kc & 3) * STB);
        uint32_t a0[4], a1[4], bn[4][4];
        ldsm_x4(a0, stg + aOff);
        ldsm_x4(a1, stg + aOff + 16 * 64);
#pragma unroll
        for (int ni = 0; ni < 4; ++ni)
            ldsm_x4(bn[ni], stg + bOff + ni * 16 * 64);
#pragma unroll
        for (int ni = 0; ni < 4; ++ni) {
            mma16816(acc[0][ni * 2 + 0], a0, bn[ni][0], bn[ni][2]);
            mma16816(acc[0][ni * 2 + 1], a0, bn[ni][1], bn[ni][3]);
            mma16816(acc[1][ni * 2 + 0], a1, bn[ni][0], bn[ni][2]);
            mma16816(acc[1][ni * 2 + 1], a1, bn[ni][1], bn[ni][3]);
        }

        if (kc + 3 < nc) {
            const int s2 = (kc + 3) & 3;
            const __nv_bfloat16* Ag  = Ab + (kc + 3) * BK + (size_t)lrow * KpA + lc * 8;
            const __nv_bfloat16* Bg0 = Bb + (kc + 3) * BK + (size_t)lrow * KpB + lc * 8;
            const __nv_bfloat16* Bg1 = Bb + (kc + 3) * BK + (size_t)(64 + lrow) * KpB + lc * 8;
            const uint32_t st = sbase + s2 * STB;
            cp_async16(st + aSt,  Ag);
            cp_async16(st + bSt0, Bg0);
            cp_async16(st + bSt1, Bg1);
        }
        cp_commit();
    }

    // ---- combine both k-groups into smem fp32 tile [64][SDP] ----
    cp_wait0();
    __syncthreads();
    float* sD = (float*)smem;

    {
        const int rr  = lane >> 2;
        const int cc0 = wn * 64 + (lane & 3) * 2;
        if (grp == 0) {
#pragma unroll
            for (int mt = 0; mt < 2; ++mt)
#pragma unroll
                for (int j = 0; j < 8; ++j) {
                    const int r0 = wm * 32 + mt * 16 + rr;
                    const int c  = cc0 + j * 8;
                    sD[r0 * SDP + c]           = acc[mt][j][0];
                    sD[r0 * SDP + c + 1]       = acc[mt][j][1];
                    sD[(r0 + 8) * SDP + c]     = acc[mt][j][2];
                    sD[(r0 + 8) * SDP + c + 1] = acc[mt][j][3];
                }
        }
        __syncthreads();
        if (grp == 1) {
#pragma unroll
            for (int mt = 0; mt < 2; ++mt)
#pragma unroll
                for (int j = 0; j < 8; ++j) {
                    const int r0 = wm * 32 + mt * 16 + rr;
                    const int c  = cc0 + j * 8;
                    sD[r0 * SDP + c]           += acc[mt][j][0];
                    sD[r0 * SDP + c + 1]       += acc[mt][j][1];
                    sD[(r0 + 8) * SDP + c]     += acc[mt][j][2];
                    sD[(r0 + 8) * SDP + c + 1] += acc[mt][j][3];
                }
        }
        __syncthreads();
    }

    // ---- cooperative stores ----
    const int r   = tid >> 2;          // 0..63
    const int cb  = (tid & 3) * 32;    // col block of 32

    if (mode == 0) {
        float* base = g_p1 + (size_t)bz * MTOT * HDIM + (size_t)(m0 + r) * HDIM + nt * 128;
#pragma unroll
        for (int e = 0; e < 8; ++e) {
            const int col = cb + e * 4;
            float4 v;
            v.x = sD[r * SDP + col];     v.y = sD[r * SDP + col + 1];
            v.z = sD[r * SDP + col + 2]; v.w = sD[r * SDP + col + 3];
            *(float4*)(base + col) = v;
        }
    } else {
        const float bv0 = bias[0], bv1 = bias[1];
        // direct tile: rows i = m0 + r, cols jc = jt*128 + col
        float* dbase = outp + ((size_t)(bz * SEQ + m0 + r)) * NJC + jt * 128;
#pragma unroll
        for (int e = 0; e < 16; ++e) {
            const int col = cb + e * 2;
            float2 v;
            v.x = sD[r * SDP + col] + bv0;
            v.y = sD[r * SDP + col + 1] + bv1;
            *(float2*)(dbase + col) = v;
        }
        if (it != jt) {
            // mirror tile: rows j = jt*64 + rj, cols 2*(m0+q)+c; value sD[q][2*rj+c]
            const int rj = r;
            float* mbase = outp + ((size_t)(bz * SEQ + jt * 64 + rj)) * NJC + m0 * 2;
            const int qb = (tid & 3) * 16;
#pragma unroll
            for (int e = 0; e < 16; ++e) {
                const int q = qb + e;
                float2 s = *(float2*)(sD + q * SDP + 2 * rj);
                float2 v;
                v.x = s.x + bv0;
                v.y = s.y + bv1;
                *(float2*)(mbase + 2 * q) = v;
            }
        }
    }
}

// ---------------------------------------------------------------------------
extern "C" void kernel_launch(void* const* d_in, const int* in_sizes, int n_in,
                              void* d_out, int out_size)
{
    const float* x  = (const float*)d_in[0];   // [4, 512, 1024]
    const float* W1 = (const float*)d_in[1];   // [256, 1024]
    const float* b1 = (const float*)d_in[2];   // [256]
    const float* W2 = (const float*)d_in[3];   // [2, 256]
    const float* b2 = (const float*)d_in[4];   // [2]
    float* out = (float*)d_out;                // [4, 512, 512, 2]

    // Prep 1: split inputs
    split_xw<<<2304, 256>>>(x, W1);

    // Stage 1 GEMM (split-K=8): p1[z] = x @ W1^T over k-window z
    gemm_kernel<<<dim3(2, 32, NSPLIT), 256, SMEM_SZ>>>(0, nullptr, nullptr);

    // Prep 2: fused reduce(+b1) + split + fold W2 into B operand
    prep_o<<<512, 256>>>(W2, b1);

    // Stage 2 GEMM (triangular): 36 block-pairs x 4 batches
    gemm_kernel<<<dim3(36, 1, BNUM), 256, SMEM_SZ>>>(1, b2, out);
}

// round 9
// speedup vs baseline: 1.1047x; 1.1047x over previous
#include <cuda_runtime.h>
#include <cuda_bf16.h>
#include <cstdint>

#define BNUM   4
#define SEQ    512
#define DMODEL 1024
#define HDIM   256
#define MTOT   2048
#define KP1    3072      // 3 * DMODEL (hi|lo|hi concat)
#define KP2    768       // 3 * HDIM
#define NJC    1024      // SEQ * 2 (j,c interleaved)
#define NSPLIT 4         // split-K factor for stage-1 GEMM
#define KSPL   (KP1 / NSPLIT)   // 768

// Scratch (allocation-free __device__ globals)
__device__ __align__(16) float         g_p1[NSPLIT * MTOT * HDIM];  // 8 MB partials
__device__ __align__(16) __nv_bfloat16 g_Xp[MTOT * KP1];            // 12 MB
__device__ __align__(16) __nv_bfloat16 g_W1p[HDIM * KP1];           // 1.5 MB
__device__ __align__(16) __nv_bfloat16 g_Ap[MTOT * KP2];            // 3 MB
__device__ __align__(16) __nv_bfloat16 g_Bp[BNUM * NJC * KP2];      // 6 MB

// ---------------------------------------------------------------------------
// helpers
// ---------------------------------------------------------------------------
static __device__ __forceinline__ uint32_t smem_u32(const void* p) {
    uint32_t a;
    asm("{ .reg .u64 t; cvta.to.shared.u64 t, %1; cvt.u32.u64 %0, t; }"
        : "=r"(a) : "l"(p));
    return a;
}
static __device__ __forceinline__ void cp_async16(uint32_t saddr, const void* gaddr) {
    asm volatile("cp.async.cg.shared.global [%0], [%1], 16;"
                 :: "r"(saddr), "l"(gaddr) : "memory");
}
static __device__ __forceinline__ void cp_commit() {
    asm volatile("cp.async.commit_group;" ::: "memory");
}
static __device__ __forceinline__ void cp_wait1() {
    asm volatile("cp.async.wait_group 1;" ::: "memory");
}
static __device__ __forceinline__ void cp_wait0() {
    asm volatile("cp.async.wait_group 0;" ::: "memory");
}
static __device__ __forceinline__ void ldsm_x4(uint32_t* r, uint32_t addr) {
    asm volatile("ldmatrix.sync.aligned.m8n8.x4.shared.b16 {%0,%1,%2,%3}, [%4];"
                 : "=r"(r[0]), "=r"(r[1]), "=r"(r[2]), "=r"(r[3]) : "r"(addr));
}
static __device__ __forceinline__ void mma16816(float* d, const uint32_t* a,
                                                uint32_t b0, uint32_t b1) {
    asm volatile(
        "mma.sync.aligned.m16n8k16.row.col.f32.bf16.bf16.f32 "
        "{%0,%1,%2,%3}, {%4,%5,%6,%7}, {%8,%9}, {%0,%1,%2,%3};"
        : "+f"(d[0]), "+f"(d[1]), "+f"(d[2]), "+f"(d[3])
        : "r"(a[0]), "r"(a[1]), "r"(a[2]), "r"(a[3]), "r"(b0), "r"(b1));
}
static __device__ __forceinline__ void st_bf2(__nv_bfloat16* p, __nv_bfloat16 a, __nv_bfloat16 b) {
    __nv_bfloat162 t; t.x = a; t.y = b;
    *(__nv_bfloat162*)p = t;
}
static __device__ __forceinline__ void split1(float v, __nv_bfloat16& h, __nv_bfloat16& l) {
    h = __float2bfloat16_rn(v);
    l = __float2bfloat16_rn(v - __bfloat162float(h));
}

// ---------------------------------------------------------------------------
// Prep 1: split X -> [hi|lo|hi], W1 -> [hi|hi|lo]
// ---------------------------------------------------------------------------
__global__ __launch_bounds__(256) void split_xw(const float* __restrict__ X,
                                                const float* __restrict__ W1) {
    const int NX4 = MTOT * DMODEL / 4;   // 524288
    int idx = blockIdx.x * 256 + threadIdx.x;
    if (idx < NX4) {
        int r = idx >> 8;
        int k = (idx & 255) * 4;
        float4 v = *(const float4*)(X + (size_t)r * DMODEL + k);
        __nv_bfloat16 h0,h1,h2,h3,l0,l1,l2,l3;
        split1(v.x,h0,l0); split1(v.y,h1,l1); split1(v.z,h2,l2); split1(v.w,h3,l3);
        __nv_bfloat16* base = g_Xp + (size_t)r * KP1 + k;
        st_bf2(base,              h0,h1); st_bf2(base+2,              h2,h3);
        st_bf2(base+DMODEL,       l0,l1); st_bf2(base+DMODEL+2,       l2,l3);
        st_bf2(base+2*DMODEL,     h0,h1); st_bf2(base+2*DMODEL+2,     h2,h3);
    } else {
        int i2 = idx - NX4;
        if (i2 >= HDIM * DMODEL / 4) return;
        int r = i2 >> 8;
        int k = (i2 & 255) * 4;
        float4 v = *(const float4*)(W1 + (size_t)r * DMODEL + k);
        __nv_bfloat16 h0,h1,h2,h3,l0,l1,l2,l3;
        split1(v.x,h0,l0); split1(v.y,h1,l1); split1(v.z,h2,l2); split1(v.w,h3,l3);
        __nv_bfloat16* base = g_W1p + (size_t)r * KP1 + k;
        st_bf2(base,              h0,h1); st_bf2(base+2,              h2,h3);
        st_bf2(base+DMODEL,       h0,h1); st_bf2(base+DMODEL+2,       h2,h3);
        st_bf2(base+2*DMODEL,     l0,l1); st_bf2(base+2*DMODEL+2,     l2,l3);
    }
}

// ---------------------------------------------------------------------------
// Prep 2 (fused reduce): o = sum_s p1[s] + b1; A' = [o_hi|o_lo|o_hi];
// B' rows jc=2j+c: v=o*w_c, [v_hi|v_hi|v_lo]
// ---------------------------------------------------------------------------
__global__ __launch_bounds__(256) void prep_o(const float* __restrict__ W2,
                                              const float* __restrict__ b1) {
    int idx = blockIdx.x * 256 + threadIdx.x;       // over 2048*64
    int m = idx >> 6;
    int h = (idx & 63) * 4;

    float4 o4 = *(const float4*)(g_p1 + (size_t)m * HDIM + h);
#pragma unroll
    for (int s = 1; s < NSPLIT; ++s) {
        float4 p = *(const float4*)(g_p1 + ((size_t)s * MTOT + m) * HDIM + h);
        o4.x += p.x; o4.y += p.y; o4.z += p.z; o4.w += p.w;
    }
    float4 bb = *(const float4*)(b1 + h);
    o4.x += bb.x; o4.y += bb.y; o4.z += bb.z; o4.w += bb.w;

    __nv_bfloat16 h0,h1,h2,h3,l0,l1,l2,l3;
    split1(o4.x,h0,l0); split1(o4.y,h1,l1); split1(o4.z,h2,l2); split1(o4.w,h3,l3);
    __nv_bfloat16* abase = g_Ap + (size_t)m * KP2 + h;
    st_bf2(abase,          h0,h1); st_bf2(abase+2,          h2,h3);
    st_bf2(abase+HDIM,     l0,l1); st_bf2(abase+HDIM+2,     l2,l3);
    st_bf2(abase+2*HDIM,   h0,h1); st_bf2(abase+2*HDIM+2,   h2,h3);

    int b = m >> 9, j = m & 511;
    float4 w0 = *(const float4*)(W2 + h);
    float4 w1 = *(const float4*)(W2 + HDIM + h);
#pragma unroll
    for (int c = 0; c < 2; ++c) {
        float4 w = c ? w1 : w0;
        float4 v;
        v.x = o4.x * w.x; v.y = o4.y * w.y; v.z = o4.z * w.z; v.w = o4.w * w.w;
        __nv_bfloat16 vh0,vh1,vh2,vh3,vl0,vl1,vl2,vl3;
        split1(v.x,vh0,vl0); split1(v.y,vh1,vl1); split1(v.z,vh2,vl2); split1(v.w,vh3,vl3);
        __nv_bfloat16* bbase = g_Bp + ((size_t)b * NJC + 2 * j + c) * KP2 + h;
        st_bf2(bbase,          vh0,vh1); st_bf2(bbase+2,          vh2,vh3);
        st_bf2(bbase+HDIM,     vh0,vh1); st_bf2(bbase+HDIM+2,     vh2,vh3);
        st_bf2(bbase+2*HDIM,   vl0,vl1); st_bf2(bbase+2*HDIM+2,   vl2,vl3);
    }
}

// ---------------------------------------------------------------------------
// mma.sync bf16 TN GEMM: D[64,64] = A[64,K] * B[64,K]^T, BK=64, 3-stage
// cp.async pipeline, 256 threads / 8 warps. Warps 0-3 consume ks 0-1 of each
// stage, warps 4-7 consume ks 2-3 (in-CTA K-split); combined via smem.
// Inner loop: batch ALL 8 ldsm first, then prefetch cp.async, then 16 MMAs
// (hides LDS latency behind the MMA burst).
// mode 0: C = g_p1[z]          (A = g_Xp, B = g_W1p, k-window z*768..)
// mode 1: C = out + b2[col&1]  (A = g_Ap, B = g_Bp)
// ---------------------------------------------------------------------------
#define BM   64
#define BN   64
#define BK   64
#define ASB  8192                     // stage bytes (A or B): 64 rows * 128B
#define BOFFB (3 * ASB)               // B region offset: 24576
#define SMEM_SZ (6 * ASB)             // 49152 bytes == default 48KB limit
#define NC   12                       // 768 / 64 for both gemms

__global__ __launch_bounds__(256, 3) void gemm_kernel(int mode,
                                                      const float* __restrict__ bias,
                                                      float* __restrict__ outp) {
    extern __shared__ char smem[];
    const uint32_t sbase = smem_u32(smem);
    const int tid = threadIdx.x;
    const int wid = tid >> 5, lane = tid & 31;
    const int grp = wid >> 2;                        // k-group 0/1
    const int wm = wid & 1, wn = (wid >> 1) & 1;     // 2x2 warp grid per group
    const int m0 = blockIdx.y * BM, n0 = blockIdx.x * BN, bz = blockIdx.z;

    const __nv_bfloat16* Ab;
    const __nv_bfloat16* Bb;
    int Kp;
    if (mode == 0) { Ab = g_Xp + (size_t)m0 * KP1 + bz * KSPL;
                     Bb = g_W1p + (size_t)n0 * KP1 + bz * KSPL; Kp = KP1; }
    else           { Ab = g_Ap + ((size_t)(bz * SEQ + m0)) * KP2;
                     Bb = g_Bp + ((size_t)(bz * NJC + n0)) * KP2; Kp = KP2; }

    // per-thread load mapping: row = tid/4, 2x16B chunks starting at (tid&3)*32B
    const int lrow = tid >> 2;
    const int lcb  = (tid & 3) * 2;                  // first chunk index (16B units)
    const int lxr  = lrow & 7;                       // swizzle key

    float acc[2][4][4];
#pragma unroll
    for (int mt = 0; mt < 2; ++mt)
#pragma unroll
        for (int j = 0; j < 4; ++j)
#pragma unroll
            for (int e = 0; e < 4; ++e) acc[mt][j][e] = 0.0f;

    // prologue: stages 0,1
#pragma unroll
    for (int s = 0; s < 2; ++s) {
        const __nv_bfloat16* Ag = Ab + s * BK + (size_t)lrow * Kp + lcb * 8;
        const __nv_bfloat16* Bg = Bb + s * BK + (size_t)lrow * Kp + lcb * 8;
        const uint32_t rowA = sbase + s * ASB + lrow * 128;
        const uint32_t rowB = rowA + BOFFB;
#pragma unroll
        for (int q = 0; q < 2; ++q) {
            const uint32_t sw = (uint32_t)(((lcb + q) ^ lxr) << 4);
            cp_async16(rowA + sw, Ag + q * 8);
            cp_async16(rowB + sw, Bg + q * 8);
        }
        cp_commit();
    }

    // ldmatrix row bases; row+16 shares the same xor (16 % 8 == 0)
    const int arow = wm * 32 + (lane & 15);
    const int brow = wn * 32 + (lane & 15);
    const int kl   = lane >> 4;                      // 16B half within k16
    const uint32_t aRow = sbase + (uint32_t)(arow * 128);
    const uint32_t bRow = sbase + BOFFB + (uint32_t)(brow * 128);
    const int axr = arow & 7, bxr = brow & 7;

    for (int kc = 0; kc < NC; ++kc) {
        cp_wait1();
        __syncthreads();

        const int s = kc % 3;
        const uint32_t aS = aRow + (uint32_t)(s * ASB);
        const uint32_t bS = bRow + (uint32_t)(s * ASB);

        // ---- batch all 8 ldsm up front ----
        uint32_t a0[2][4], a1[2][4], b0[2][4], b1[2][4];
#pragma unroll
        for (int ksi = 0; ksi < 2; ++ksi) {
            const int c16 = (grp * 2 + ksi) * 2 + kl;
            const uint32_t swa = (uint32_t)((c16 ^ axr) << 4);
            const uint32_t swb = (uint32_t)((c16 ^ bxr) << 4);
            ldsm_x4(a0[ksi], aS + swa);
            ldsm_x4(a1[ksi], aS + 16 * 128 + swa);
            ldsm_x4(b0[ksi], bS + swb);
            ldsm_x4(b1[ksi], bS + 16 * 128 + swb);
        }

        // ---- prefetch kc+2 while MMAs run ----
        if (kc + 2 < NC) {
            const int s2 = (kc + 2) % 3;
            const __nv_bfloat16* Ag = Ab + (kc + 2) * BK + (size_t)lrow * Kp + lcb * 8;
            const __nv_bfloat16* Bg = Bb + (kc + 2) * BK + (size_t)lrow * Kp + lcb * 8;
            const uint32_t rowA = sbase + s2 * ASB + lrow * 128;
            const uint32_t rowB = rowA + BOFFB;
#pragma unroll
            for (int q = 0; q < 2; ++q) {
                const uint32_t sw = (uint32_t)(((lcb + q) ^ lxr) << 4);
                cp_async16(rowA + sw, Ag + q * 8);
                cp_async16(rowB + sw, Bg + q * 8);
            }
        }
        cp_commit();

        // ---- 16 MMAs ----
#pragma unroll
        for (int ksi = 0; ksi < 2; ++ksi) {
            mma16816(acc[0][0], a0[ksi], b0[ksi][0], b0[ksi][2]);
            mma16816(acc[0][1], a0[ksi], b0[ksi][1], b0[ksi][3]);
            mma16816(acc[0][2], a0[ksi], b1[ksi][0], b1[ksi][2]);
            mma16816(acc[0][3], a0[ksi], b1[ksi][1], b1[ksi][3]);
            mma16816(acc[1][0], a1[ksi], b0[ksi][0], b0[ksi][2]);
            mma16816(acc[1][1], a1[ksi], b0[ksi][1], b0[ksi][3]);
            mma16816(acc[1][2], a1[ksi], b1[ksi][0], b1[ksi][2]);
            mma16816(acc[1][3], a1[ksi], b1[ksi][1], b1[ksi][3]);
        }
    }

    // ---- combine the two k-groups through smem, then store (group 0) ----
    cp_wait0();
    __syncthreads();

    float* sC = (float*)smem;                        // 64 x 66 fp32 = 16.9KB
    const int rr = lane >> 2;                        // 0..7
    const int cc0 = wn * 32 + (lane & 3) * 2;        // col base

    if (grp == 1) {
#pragma unroll
        for (int mt = 0; mt < 2; ++mt)
#pragma unroll
            for (int j = 0; j < 4; ++j) {
                const int r0 = wm * 32 + rr + mt * 16;
                const int c  = cc0 + j * 8;
                float2 v0; v0.x = acc[mt][j][0]; v0.y = acc[mt][j][1];
                float2 v1; v1.x = acc[mt][j][2]; v1.y = acc[mt][j][3];
                *(float2*)(sC + r0 * 66 + c)       = v0;
                *(float2*)(sC + (r0 + 8) * 66 + c) = v1;
            }
    }
    __syncthreads();

    if (grp == 0) {
        const int row0 = m0 + wm * 32 + rr;
        const int col0 = n0 + cc0;
        float bv0 = 0.f, bv1 = 0.f;
        if (mode == 1) { bv0 = bias[0]; bv1 = bias[1]; }
#pragma unroll
        for (int mt = 0; mt < 2; ++mt) {
#pragma unroll
            for (int j = 0; j < 4; ++j) {
                const int lr0 = wm * 32 + rr + mt * 16;
                const int lc2 = cc0 + j * 8;
                float2 p0 = *(float2*)(sC + lr0 * 66 + lc2);
                float2 p1 = *(float2*)(sC + (lr0 + 8) * 66 + lc2);
                const int col = col0 + j * 8;
                const int r0 = row0 + mt * 16;
                if (mode == 0) {
                    float* base = g_p1 + (size_t)bz * MTOT * HDIM;
                    float2 v0; v0.x = acc[mt][j][0] + p0.x; v0.y = acc[mt][j][1] + p0.y;
                    float2 v1; v1.x = acc[mt][j][2] + p1.x; v1.y = acc[mt][j][3] + p1.y;
                    *(float2*)(base + (size_t)r0 * HDIM + col)       = v0;
                    *(float2*)(base + (size_t)(r0 + 8) * HDIM + col) = v1;
                } else {
                    float2 v0; v0.x = acc[mt][j][0] + p0.x + bv0; v0.y = acc[mt][j][1] + p0.y + bv1;
                    float2 v1; v1.x = acc[mt][j][2] + p1.x + bv0; v1.y = acc[mt][j][3] + p1.y + bv1;
                    float* base = outp + ((size_t)bz * SEQ) * NJC;
                    *(float2*)(base + (size_t)r0 * NJC + col)       = v0;
                    *(float2*)(base + (size_t)(r0 + 8) * NJC + col) = v1;
                }
            }
        }
    }
}

// ---------------------------------------------------------------------------
extern "C" void kernel_launch(void* const* d_in, const int* in_sizes, int n_in,
                              void* d_out, int out_size)
{
    const float* x  = (const float*)d_in[0];   // [4, 512, 1024]
    const float* W1 = (const float*)d_in[1];   // [256, 1024]
    const float* b1 = (const float*)d_in[2];   // [256]
    const float* W2 = (const float*)d_in[3];   // [2, 256]
    const float* b2 = (const float*)d_in[4];   // [2]
    float* out = (float*)d_out;                // [4, 512, 512, 2]

    // Prep 1: split inputs
    split_xw<<<2304, 256>>>(x, W1);

    // Stage 1 GEMM (split-K=4): p1[z] = x @ W1^T over k-window z
    gemm_kernel<<<dim3(HDIM / BN, MTOT / BM, NSPLIT), 256, SMEM_SZ>>>(0, nullptr, nullptr);

    // Prep 2: fused reduce(+b1) + split + fold W2 into B operand
    prep_o<<<512, 256>>>(W2, b1);

    // Stage 2 GEMM: out[b,i,jc] = A @ B'^T + b2  (M=512, N=1024, K'=768) x4
    gemm_kernel<<<dim3(NJC / BN, SEQ / BM, BNUM), 256, SMEM_SZ>>>(1, b2, out);
}

// round 10
// speedup vs baseline: 1.4308x; 1.2952x over previous
#include <cuda_runtime.h>
#include <cuda_fp16.h>
#include <cstdint>

#define BNUM   4
#define SEQ    512
#define DMODEL 1024
#define HDIM   256
#define MTOT   2048
#define KP1    2048      // 2 * DMODEL (x_hi|x_lo concat)
#define KP2    512       // 2 * HDIM
#define NJC    1024      // SEQ * 2 (j,c interleaved)
#define NSPLIT 4         // split-K factor for stage-1 GEMM
#define KSPL   (KP1 / NSPLIT)   // 512

// Scratch (allocation-free __device__ globals)
__device__ __align__(16) float  g_p1[NSPLIT * MTOT * HDIM];  // 8 MB partials
__device__ __align__(16) __half g_Xp[MTOT * KP1];            // 8 MB
__device__ __align__(16) __half g_W1p[HDIM * KP1];           // 1 MB
__device__ __align__(16) __half g_Ap[MTOT * KP2];            // 2 MB
__device__ __align__(16) __half g_Bp[BNUM * NJC * KP2];      // 4 MB

// ---------------------------------------------------------------------------
// helpers
// ---------------------------------------------------------------------------
static __device__ __forceinline__ uint32_t smem_u32(const void* p) {
    uint32_t a;
    asm("{ .reg .u64 t; cvta.to.shared.u64 t, %1; cvt.u32.u64 %0, t; }"
        : "=r"(a) : "l"(p));
    return a;
}
static __device__ __forceinline__ void cp_async16(uint32_t saddr, const void* gaddr) {
    asm volatile("cp.async.cg.shared.global [%0], [%1], 16;"
                 :: "r"(saddr), "l"(gaddr) : "memory");
}
static __device__ __forceinline__ void cp_commit() {
    asm volatile("cp.async.commit_group;" ::: "memory");
}
static __device__ __forceinline__ void cp_wait1() {
    asm volatile("cp.async.wait_group 1;" ::: "memory");
}
static __device__ __forceinline__ void cp_wait0() {
    asm volatile("cp.async.wait_group 0;" ::: "memory");
}
static __device__ __forceinline__ void ldsm_x4(uint32_t* r, uint32_t addr) {
    asm volatile("ldmatrix.sync.aligned.m8n8.x4.shared.b16 {%0,%1,%2,%3}, [%4];"
                 : "=r"(r[0]), "=r"(r[1]), "=r"(r[2]), "=r"(r[3]) : "r"(addr));
}
static __device__ __forceinline__ void mma16816(float* d, const uint32_t* a,
                                                uint32_t b0, uint32_t b1) {
    asm volatile(
        "mma.sync.aligned.m16n8k16.row.col.f32.f16.f16.f32 "
        "{%0,%1,%2,%3}, {%4,%5,%6,%7}, {%8,%9}, {%0,%1,%2,%3};"
        : "+f"(d[0]), "+f"(d[1]), "+f"(d[2]), "+f"(d[3])
        : "r"(a[0]), "r"(a[1]), "r"(a[2]), "r"(a[3]), "r"(b0), "r"(b1));
}
static __device__ __forceinline__ void st_h2(__half* p, __half a, __half b) {
    __half2 t; t.x = a; t.y = b;
    *(__half2*)p = t;
}
static __device__ __forceinline__ void split1(float v, __half& h, __half& l) {
    h = __float2half_rn(v);
    l = __float2half_rn(v - __half2float(h));
}

// ---------------------------------------------------------------------------
// Prep 1: X -> [x_hi | x_lo], W1 -> [w_hi | w_hi]
// ---------------------------------------------------------------------------
__global__ __launch_bounds__(256) void split_xw(const float* __restrict__ X,
                                                const float* __restrict__ W1) {
    const int NX4 = MTOT * DMODEL / 4;   // 524288
    int idx = blockIdx.x * 256 + threadIdx.x;
    if (idx < NX4) {
        int r = idx >> 8;
        int k = (idx & 255) * 4;
        float4 v = *(const float4*)(X + (size_t)r * DMODEL + k);
        __half h0,h1,h2,h3,l0,l1,l2,l3;
        split1(v.x,h0,l0); split1(v.y,h1,l1); split1(v.z,h2,l2); split1(v.w,h3,l3);
        __half* base = g_Xp + (size_t)r * KP1 + k;
        st_h2(base,          h0,h1); st_h2(base+2,          h2,h3);
        st_h2(base+DMODEL,   l0,l1); st_h2(base+DMODEL+2,   l2,l3);
    } else {
        int i2 = idx - NX4;
        if (i2 >= HDIM * DMODEL / 4) return;
        int r = i2 >> 8;
        int k = (i2 & 255) * 4;
        float4 v = *(const float4*)(W1 + (size_t)r * DMODEL + k);
        __half h0 = __float2half_rn(v.x), h1 = __float2half_rn(v.y);
        __half h2 = __float2half_rn(v.z), h3 = __float2half_rn(v.w);
        __half* base = g_W1p + (size_t)r * KP1 + k;
        st_h2(base,          h0,h1); st_h2(base+2,          h2,h3);
        st_h2(base+DMODEL,   h0,h1); st_h2(base+DMODEL+2,   h2,h3);
    }
}

// ---------------------------------------------------------------------------
// Prep 2 (fused reduce): o = sum_s p1[s] + b1; A' = [o_hi | o_lo];
// B' rows jc=2j+c: v = o * w_c, [v_hi | v_hi]
// ---------------------------------------------------------------------------
__global__ __launch_bounds__(256) void prep_o(const float* __restrict__ W2,
                                              const float* __restrict__ b1) {
    int idx = blockIdx.x * 256 + threadIdx.x;       // over 2048*64
    int m = idx >> 6;
    int h = (idx & 63) * 4;

    float4 o4 = *(const float4*)(g_p1 + (size_t)m * HDIM + h);
#pragma unroll
    for (int s = 1; s < NSPLIT; ++s) {
        float4 p = *(const float4*)(g_p1 + ((size_t)s * MTOT + m) * HDIM + h);
        o4.x += p.x; o4.y += p.y; o4.z += p.z; o4.w += p.w;
    }
    float4 bb = *(const float4*)(b1 + h);
    o4.x += bb.x; o4.y += bb.y; o4.z += bb.z; o4.w += bb.w;

    __half h0,h1,h2,h3,l0,l1,l2,l3;
    split1(o4.x,h0,l0); split1(o4.y,h1,l1); split1(o4.z,h2,l2); split1(o4.w,h3,l3);
    __half* abase = g_Ap + (size_t)m * KP2 + h;
    st_h2(abase,        h0,h1); st_h2(abase+2,        h2,h3);
    st_h2(abase+HDIM,   l0,l1); st_h2(abase+HDIM+2,   l2,l3);

    int b = m >> 9, j = m & 511;
    float4 w0 = *(const float4*)(W2 + h);
    float4 w1 = *(const float4*)(W2 + HDIM + h);
#pragma unroll
    for (int c = 0; c < 2; ++c) {
        float4 w = c ? w1 : w0;
        __half v0 = __float2half_rn(o4.x * w.x);
        __half v1 = __float2half_rn(o4.y * w.y);
        __half v2 = __float2half_rn(o4.z * w.z);
        __half v3 = __float2half_rn(o4.w * w.w);
        __half* bbase = g_Bp + ((size_t)b * NJC + 2 * j + c) * KP2 + h;
        st_h2(bbase,        v0,v1); st_h2(bbase+2,        v2,v3);
        st_h2(bbase+HDIM,   v0,v1); st_h2(bbase+HDIM+2,   v2,v3);
    }
}

// ---------------------------------------------------------------------------
// mma.sync fp16 TN GEMM: D[64,64] = A[64,K] * B[64,K]^T, BK=64, 3-stage
// cp.async pipeline, 256 threads / 8 warps. Warps 0-3 consume ks 0-1 of each
// stage, warps 4-7 consume ks 2-3 (in-CTA K-split); combined via smem.
// mode 0: C = g_p1[z]          (A = g_Xp, B = g_W1p, k-window z*512..)
// mode 1: C = out + b2[col&1]  (A = g_Ap, B = g_Bp)
// ---------------------------------------------------------------------------
#define BM   64
#define BN   64
#define BK   64
#define ASB  8192                     // stage bytes (A or B): 64 rows * 128B
#define BOFFB (3 * ASB)               // B region offset: 24576
#define SMEM_SZ (6 * ASB)             // 49152 bytes == default 48KB limit
#define NC   8                        // 512 / 64 for both gemms

__global__ __launch_bounds__(256, 4) void gemm_kernel(int mode,
                                                      const float* __restrict__ bias,
                                                      float* __restrict__ outp) {
    extern __shared__ char smem[];
    const uint32_t sbase = smem_u32(smem);
    const int tid = threadIdx.x;
    const int wid = tid >> 5, lane = tid & 31;
    const int grp = wid >> 2;                        // k-group 0/1
    const int wm = wid & 1, wn = (wid >> 1) & 1;     // 2x2 warp grid per group
    const int m0 = blockIdx.y * BM, n0 = blockIdx.x * BN, bz = blockIdx.z;

    const __half* Ab;
    const __half* Bb;
    int Kp;
    if (mode == 0) { Ab = g_Xp + (size_t)m0 * KP1 + bz * KSPL;
                     Bb = g_W1p + (size_t)n0 * KP1 + bz * KSPL; Kp = KP1; }
    else           { Ab = g_Ap + ((size_t)(bz * SEQ + m0)) * KP2;
                     Bb = g_Bp + ((size_t)(bz * NJC + n0)) * KP2; Kp = KP2; }

    // per-thread load mapping: row = tid/4, 2x16B chunks starting at (tid&3)*32B
    const int lrow = tid >> 2;
    const int lcb  = (tid & 3) * 2;                  // first chunk index (16B units)
    const int lxr  = lrow & 7;                       // swizzle key

    float acc[2][4][4];
#pragma unroll
    for (int mt = 0; mt < 2; ++mt)
#pragma unroll
        for (int j = 0; j < 4; ++j)
#pragma unroll
            for (int e = 0; e < 4; ++e) acc[mt][j][e] = 0.0f;

    // prologue: stages 0,1
#pragma unroll
    for (int s = 0; s < 2; ++s) {
        const __half* Ag = Ab + s * BK + (size_t)lrow * Kp + lcb * 8;
        const __half* Bg = Bb + s * BK + (size_t)lrow * Kp + lcb * 8;
        const uint32_t rowA = sbase + s * ASB + lrow * 128;
        const uint32_t rowB = rowA + BOFFB;
#pragma unroll
        for (int q = 0; q < 2; ++q) {
            const uint32_t sw = (uint32_t)(((lcb + q) ^ lxr) << 4);
            cp_async16(rowA + sw, Ag + q * 8);
            cp_async16(rowB + sw, Bg + q * 8);
        }
        cp_commit();
    }

    // ldmatrix row bases; row+16 shares the same xor (16 % 8 == 0)
    const int arow = wm * 32 + (lane & 15);
    const int brow = wn * 32 + (lane & 15);
    const int kl   = lane >> 4;                      // 16B half within k16
    const uint32_t aRow = sbase + (uint32_t)(arow * 128);
    const uint32_t bRow = sbase + BOFFB + (uint32_t)(brow * 128);
    const int axr = arow & 7, bxr = brow & 7;

    for (int kc = 0; kc < NC; ++kc) {
        cp_wait1();
        __syncthreads();

        const int s = kc % 3;
        const uint32_t aS = aRow + (uint32_t)(s * ASB);
        const uint32_t bS = bRow + (uint32_t)(s * ASB);
#pragma unroll
        for (int ksi = 0; ksi < 2; ++ksi) {
            const int c16 = (grp * 2 + ksi) * 2 + kl;
            const uint32_t swa = (uint32_t)((c16 ^ axr) << 4);
            const uint32_t swb = (uint32_t)((c16 ^ bxr) << 4);
            uint32_t a0[4], a1[4], b0[4], b1[4];
            ldsm_x4(a0, aS + swa);
            ldsm_x4(a1, aS + 16 * 128 + swa);
            ldsm_x4(b0, bS + swb);
            ldsm_x4(b1, bS + 16 * 128 + swb);
            mma16816(acc[0][0], a0, b0[0], b0[2]);
            mma16816(acc[0][1], a0, b0[1], b0[3]);
            mma16816(acc[0][2], a0, b1[0], b1[2]);
            mma16816(acc[0][3], a0, b1[1], b1[3]);
            mma16816(acc[1][0], a1, b0[0], b0[2]);
            mma16816(acc[1][1], a1, b0[1], b0[3]);
            mma16816(acc[1][2], a1, b1[0], b1[2]);
            mma16816(acc[1][3], a1, b1[1], b1[3]);
        }

        if (kc + 2 < NC) {
            const int s2 = (kc + 2) % 3;
            const __half* Ag = Ab + (kc + 2) * BK + (size_t)lrow * Kp + lcb * 8;
            const __half* Bg = Bb + (kc + 2) * BK + (size_t)lrow * Kp + lcb * 8;
            const uint32_t rowA = sbase + s2 * ASB + lrow * 128;
            const uint32_t rowB = rowA + BOFFB;
#pragma unroll
            for (int q = 0; q < 2; ++q) {
                const uint32_t sw = (uint32_t)(((lcb + q) ^ lxr) << 4);
                cp_async16(rowA + sw, Ag + q * 8);
                cp_async16(rowB + sw, Bg + q * 8);
            }
        }
        cp_commit();
    }

    // ---- combine the two k-groups through smem, then store (group 0) ----
    cp_wait0();
    __syncthreads();

    float* sC = (float*)smem;                        // 64 x 66 fp32 = 16.9KB
    const int rr = lane >> 2;                        // 0..7
    const int cc0 = wn * 32 + (lane & 3) * 2;        // col base

    if (grp == 1) {
#pragma unroll
        for (int mt = 0; mt < 2; ++mt)
#pragma unroll
            for (int j = 0; j < 4; ++j) {
                const int r0 = wm * 32 + rr + mt * 16;
                const int c  = cc0 + j * 8;
                float2 v0; v0.x = acc[mt][j][0]; v0.y = acc[mt][j][1];
                float2 v1; v1.x = acc[mt][j][2]; v1.y = acc[mt][j][3];
                *(float2*)(sC + r0 * 66 + c)       = v0;
                *(float2*)(sC + (r0 + 8) * 66 + c) = v1;
            }
    }
    __syncthreads();

    if (grp == 0) {
        const int row0 = m0 + wm * 32 + rr;
        const int col0 = n0 + cc0;
        float bv0 = 0.f, bv1 = 0.f;
        if (mode == 1) { bv0 = bias[0]; bv1 = bias[1]; }
#pragma unroll
        for (int mt = 0; mt < 2; ++mt) {
#pragma unroll
            for (int j = 0; j < 4; ++j) {
                const int lr0 = wm * 32 + rr + mt * 16;
                const int lc2 = cc0 + j * 8;
                float2 p0 = *(float2*)(sC + lr0 * 66 + lc2);
                float2 p1 = *(float2*)(sC + (lr0 + 8) * 66 + lc2);
                const int col = col0 + j * 8;
                const int r0 = row0 + mt * 16;
                if (mode == 0) {
                    float* base = g_p1 + (size_t)bz * MTOT * HDIM;
                    float2 v0; v0.x = acc[mt][j][0] + p0.x; v0.y = acc[mt][j][1] + p0.y;
                    float2 v1; v1.x = acc[mt][j][2] + p1.x; v1.y = acc[mt][j][3] + p1.y;
                    *(float2*)(base + (size_t)r0 * HDIM + col)       = v0;
                    *(float2*)(base + (size_t)(r0 + 8) * HDIM + col) = v1;
                } else {
                    float2 v0; v0.x = acc[mt][j][0] + p0.x + bv0; v0.y = acc[mt][j][1] + p0.y + bv1;
                    float2 v1; v1.x = acc[mt][j][2] + p1.x + bv0; v1.y = acc[mt][j][3] + p1.y + bv1;
                    float* base = outp + ((size_t)bz * SEQ) * NJC;
                    *(float2*)(base + (size_t)r0 * NJC + col)       = v0;
                    *(float2*)(base + (size_t)(r0 + 8) * NJC + col) = v1;
                }
            }
        }
    }
}

// ---------------------------------------------------------------------------
extern "C" void kernel_launch(void* const* d_in, const int* in_sizes, int n_in,
                              void* d_out, int out_size)
{
    const float* x  = (const float*)d_in[0];   // [4, 512, 1024]
    const float* W1 = (const float*)d_in[1];   // [256, 1024]
    const float* b1 = (const float*)d_in[2];   // [256]
    const float* W2 = (const float*)d_in[3];   // [2, 256]
    const float* b2 = (const float*)d_in[4];   // [2]
    float* out = (float*)d_out;                // [4, 512, 512, 2]

    // Prep 1: split inputs (fp16 2-term)
    split_xw<<<2304, 256>>>(x, W1);

    // Stage 1 GEMM (split-K=4): p1[z] = x @ W1^T over k-window z
    gemm_kernel<<<dim3(HDIM / BN, MTOT / BM, NSPLIT), 256, SMEM_SZ>>>(0, nullptr, nullptr);

    // Prep 2: fused reduce(+b1) + split + fold W2 into B operand
    prep_o<<<512, 256>>>(W2, b1);

    // Stage 2 GEMM: out[b,i,jc] = A @ B'^T + b2  (M=512, N=1024, K'=512) x4
    gemm_kernel<<<dim3(NJC / BN, SEQ / BM, BNUM), 256, SMEM_SZ>>>(1, b2, out);
}

// round 11
// speedup vs baseline: 1.5246x; 1.0656x over previous
#include <cuda_runtime.h>
#include <cuda_fp16.h>
#include <cstdint>

#define BNUM   4
#define SEQ    512
#define DMODEL 1024
#define HDIM   256
#define MTOT   2048
#define KP1    2048      // 2 * DMODEL (x_hi|x_lo concat)
#define KP2    512       // 2 * HDIM
#define NJC    1024      // SEQ * 2 (j,c interleaved)
#define NSPLIT 4         // split-K factor for stage-1 GEMM
#define KSPL   (KP1 / NSPLIT)   // 512

// Scratch (allocation-free __device__ globals)
__device__ __align__(16) float  g_p1[NSPLIT * MTOT * HDIM];  // 8 MB partials
__device__ __align__(16) __half g_Xp[MTOT * KP1];            // 8 MB
__device__ __align__(16) __half g_W1p[HDIM * KP1];           // 1 MB
__device__ __align__(16) __half g_Ap[MTOT * KP2];            // 2 MB
__device__ __align__(16) __half g_Bp[BNUM * NJC * KP2];      // 4 MB

// ---------------------------------------------------------------------------
// helpers
// ---------------------------------------------------------------------------
static __device__ __forceinline__ uint32_t smem_u32(const void* p) {
    uint32_t a;
    asm("{ .reg .u64 t; cvta.to.shared.u64 t, %1; cvt.u32.u64 %0, t; }"
        : "=r"(a) : "l"(p));
    return a;
}
static __device__ __forceinline__ void cp_async16(uint32_t saddr, const void* gaddr) {
    asm volatile("cp.async.cg.shared.global [%0], [%1], 16;"
                 :: "r"(saddr), "l"(gaddr) : "memory");
}
static __device__ __forceinline__ void cp_commit() {
    asm volatile("cp.async.commit_group;" ::: "memory");
}
static __device__ __forceinline__ void cp_wait1() {
    asm volatile("cp.async.wait_group 1;" ::: "memory");
}
static __device__ __forceinline__ void cp_wait0() {
    asm volatile("cp.async.wait_group 0;" ::: "memory");
}
static __device__ __forceinline__ void ldsm_x4(uint32_t* r, uint32_t addr) {
    asm volatile("ldmatrix.sync.aligned.m8n8.x4.shared.b16 {%0,%1,%2,%3}, [%4];"
                 : "=r"(r[0]), "=r"(r[1]), "=r"(r[2]), "=r"(r[3]) : "r"(addr));
}
static __device__ __forceinline__ void mma16816(float* d, const uint32_t* a,
                                                uint32_t b0, uint32_t b1) {
    asm volatile(
        "mma.sync.aligned.m16n8k16.row.col.f32.f16.f16.f32 "
        "{%0,%1,%2,%3}, {%4,%5,%6,%7}, {%8,%9}, {%0,%1,%2,%3};"
        : "+f"(d[0]), "+f"(d[1]), "+f"(d[2]), "+f"(d[3])
        : "r"(a[0]), "r"(a[1]), "r"(a[2]), "r"(a[3]), "r"(b0), "r"(b1));
}
static __device__ __forceinline__ void st_h2(__half* p, __half a, __half b) {
    __half2 t; t.x = a; t.y = b;
    *(__half2*)p = t;
}
static __device__ __forceinline__ void split1(float v, __half& h, __half& l) {
    h = __float2half_rn(v);
    l = __float2half_rn(v - __half2float(h));
}

// ---------------------------------------------------------------------------
// Prep 1: X -> [x_hi | x_lo], W1 -> [w_hi | w_hi]
// ---------------------------------------------------------------------------
__global__ __launch_bounds__(256) void split_xw(const float* __restrict__ X,
                                                const float* __restrict__ W1) {
    const int NX4 = MTOT * DMODEL / 4;   // 524288
    int idx = blockIdx.x * 256 + threadIdx.x;
    if (idx < NX4) {
        int r = idx >> 8;
        int k = (idx & 255) * 4;
        float4 v = *(const float4*)(X + (size_t)r * DMODEL + k);
        __half h0,h1,h2,h3,l0,l1,l2,l3;
        split1(v.x,h0,l0); split1(v.y,h1,l1); split1(v.z,h2,l2); split1(v.w,h3,l3);
        __half* base = g_Xp + (size_t)r * KP1 + k;
        st_h2(base,          h0,h1); st_h2(base+2,          h2,h3);
        st_h2(base+DMODEL,   l0,l1); st_h2(base+DMODEL+2,   l2,l3);
    } else {
        int i2 = idx - NX4;
        if (i2 >= HDIM * DMODEL / 4) return;
        int r = i2 >> 8;
        int k = (i2 & 255) * 4;
        float4 v = *(const float4*)(W1 + (size_t)r * DMODEL + k);
        __half h0 = __float2half_rn(v.x), h1 = __float2half_rn(v.y);
        __half h2 = __float2half_rn(v.z), h3 = __float2half_rn(v.w);
        __half* base = g_W1p + (size_t)r * KP1 + k;
        st_h2(base,          h0,h1); st_h2(base+2,          h2,h3);
        st_h2(base+DMODEL,   h0,h1); st_h2(base+DMODEL+2,   h2,h3);
    }
}

// ---------------------------------------------------------------------------
// Prep 2 (fused reduce): o = sum_s p1[s] + b1; A' = [o_hi | o_lo];
// B' rows jc=2j+c: v = o * w_c, [v_hi | v_hi]
// ---------------------------------------------------------------------------
__global__ __launch_bounds__(256) void prep_o(const float* __restrict__ W2,
                                              const float* __restrict__ b1) {
    int idx = blockIdx.x * 256 + threadIdx.x;       // over 2048*64
    int m = idx >> 6;
    int h = (idx & 63) * 4;

    float4 o4 = *(const float4*)(g_p1 + (size_t)m * HDIM + h);
#pragma unroll
    for (int s = 1; s < NSPLIT; ++s) {
        float4 p = *(const float4*)(g_p1 + ((size_t)s * MTOT + m) * HDIM + h);
        o4.x += p.x; o4.y += p.y; o4.z += p.z; o4.w += p.w;
    }
    float4 bb = *(const float4*)(b1 + h);
    o4.x += bb.x; o4.y += bb.y; o4.z += bb.z; o4.w += bb.w;

    __half h0,h1,h2,h3,l0,l1,l2,l3;
    split1(o4.x,h0,l0); split1(o4.y,h1,l1); split1(o4.z,h2,l2); split1(o4.w,h3,l3);
    __half* abase = g_Ap + (size_t)m * KP2 + h;
    st_h2(abase,        h0,h1); st_h2(abase+2,        h2,h3);
    st_h2(abase+HDIM,   l0,l1); st_h2(abase+HDIM+2,   l2,l3);

    int b = m >> 9, j = m & 511;
    float4 w0 = *(const float4*)(W2 + h);
    float4 w1 = *(const float4*)(W2 + HDIM + h);
#pragma unroll
    for (int c = 0; c < 2; ++c) {
        float4 w = c ? w1 : w0;
        __half v0 = __float2half_rn(o4.x * w.x);
        __half v1 = __float2half_rn(o4.y * w.y);
        __half v2 = __float2half_rn(o4.z * w.z);
        __half v3 = __float2half_rn(o4.w * w.w);
        __half* bbase = g_Bp + ((size_t)b * NJC + 2 * j + c) * KP2 + h;
        st_h2(bbase,        v0,v1); st_h2(bbase+2,        v2,v3);
        st_h2(bbase+HDIM,   v0,v1); st_h2(bbase+HDIM+2,   v2,v3);
    }
}

// ---------------------------------------------------------------------------
// mma.sync fp16 TN GEMM: D[64,64] = A[64,K] * B[64,K]^T, BK=64, 3-stage
// cp.async pipeline, 256 threads / 8 warps. Warps 0-3 consume ks 0-1 of each
// stage, warps 4-7 consume ks 2-3 (in-CTA K-split); combined via smem.
// mode 0: grid (4, 32, NSPLIT); C = g_p1[z] (k-window z*512..)
// mode 1: TRIANGULAR grid (2, 36, 4): blockIdx.y = pair (it<=jt) over 8x8
//   64-row blocks, blockIdx.x = jc half. Computes 64 i-rows x 64 jc-cols;
//   off-diagonal pairs also write the mirrored tile out[b,j,i,c] from the
//   smem-staged fp32 tile (out is symmetric in i,j).
// ---------------------------------------------------------------------------
#define BM   64
#define BN   64
#define BK   64
#define ASB  8192                     // stage bytes (A or B): 64 rows * 128B
#define BOFFB (3 * ASB)               // B region offset: 24576
#define SMEM_SZ (6 * ASB)             // 49152 bytes == default 48KB limit
#define NC   8                        // 512 / 64 for both gemms
#define SDP  66                       // fp32 combine-tile pitch

__global__ __launch_bounds__(256, 4) void gemm_kernel(int mode,
                                                      const float* __restrict__ bias,
                                                      float* __restrict__ outp) {
    extern __shared__ char smem[];
    const uint32_t sbase = smem_u32(smem);
    const int tid = threadIdx.x;
    const int wid = tid >> 5, lane = tid & 31;
    const int grp = wid >> 2;                        // k-group 0/1
    const int wm = wid & 1, wn = (wid >> 1) & 1;     // 2x2 warp grid per group
    const int bz = blockIdx.z;

    int m0, n0, it = 0, jt = 0, half = 0;
    if (mode == 0) {
        m0 = blockIdx.y * BM;
        n0 = blockIdx.x * BN;
    } else {
        half = blockIdx.x;
        int p = blockIdx.y;                          // 0..35
        jt = 0;
        while (((jt + 1) * (jt + 2) >> 1) <= p) ++jt;
        it = p - ((jt * (jt + 1)) >> 1);
        m0 = it * 64;
        n0 = jt * 128 + half * 64;
    }

    const __half* Ab;
    const __half* Bb;
    int Kp;
    if (mode == 0) { Ab = g_Xp + (size_t)m0 * KP1 + bz * KSPL;
                     Bb = g_W1p + (size_t)n0 * KP1 + bz * KSPL; Kp = KP1; }
    else           { Ab = g_Ap + ((size_t)(bz * SEQ + m0)) * KP2;
                     Bb = g_Bp + ((size_t)(bz * NJC + n0)) * KP2; Kp = KP2; }

    // per-thread load mapping: row = tid/4, 2x16B chunks starting at (tid&3)*32B
    const int lrow = tid >> 2;
    const int lcb  = (tid & 3) * 2;                  // first chunk index (16B units)
    const int lxr  = lrow & 7;                       // swizzle key

    float acc[2][4][4];
#pragma unroll
    for (int mt = 0; mt < 2; ++mt)
#pragma unroll
        for (int j = 0; j < 4; ++j)
#pragma unroll
            for (int e = 0; e < 4; ++e) acc[mt][j][e] = 0.0f;

    // prologue: stages 0,1
#pragma unroll
    for (int s = 0; s < 2; ++s) {
        const __half* Ag = Ab + s * BK + (size_t)lrow * Kp + lcb * 8;
        const __half* Bg = Bb + s * BK + (size_t)lrow * Kp + lcb * 8;
        const uint32_t rowA = sbase + s * ASB + lrow * 128;
        const uint32_t rowB = rowA + BOFFB;
#pragma unroll
        for (int q = 0; q < 2; ++q) {
            const uint32_t sw = (uint32_t)(((lcb + q) ^ lxr) << 4);
            cp_async16(rowA + sw, Ag + q * 8);
            cp_async16(rowB + sw, Bg + q * 8);
        }
        cp_commit();
    }

    // ldmatrix row bases; row+16 shares the same xor (16 % 8 == 0)
    const int arow = wm * 32 + (lane & 15);
    const int brow = wn * 32 + (lane & 15);
    const int kl   = lane >> 4;                      // 16B half within k16
    const uint32_t aRow = sbase + (uint32_t)(arow * 128);
    const uint32_t bRow = sbase + BOFFB + (uint32_t)(brow * 128);
    const int axr = arow & 7, bxr = brow & 7;

    for (int kc = 0; kc < NC; ++kc) {
        cp_wait1();
        __syncthreads();

        const int s = kc % 3;
        const uint32_t aS = aRow + (uint32_t)(s * ASB);
        const uint32_t bS = bRow + (uint32_t)(s * ASB);
#pragma unroll
        for (int ksi = 0; ksi < 2; ++ksi) {
            const int c16 = (grp * 2 + ksi) * 2 + kl;
            const uint32_t swa = (uint32_t)((c16 ^ axr) << 4);
            const uint32_t swb = (uint32_t)((c16 ^ bxr) << 4);
            uint32_t a0[4], a1[4], b0[4], b1[4];
            ldsm_x4(a0, aS + swa);
            ldsm_x4(a1, aS + 16 * 128 + swa);
            ldsm_x4(b0, bS + swb);
            ldsm_x4(b1, bS + 16 * 128 + swb);
            mma16816(acc[0][0], a0, b0[0], b0[2]);
            mma16816(acc[0][1], a0, b0[1], b0[3]);
            mma16816(acc[0][2], a0, b1[0], b1[2]);
            mma16816(acc[0][3], a0, b1[1], b1[3]);
            mma16816(acc[1][0], a1, b0[0], b0[2]);
            mma16816(acc[1][1], a1, b0[1], b0[3]);
            mma16816(acc[1][2], a1, b1[0], b1[2]);
            mma16816(acc[1][3], a1, b1[1], b1[3]);
        }

        if (kc + 2 < NC) {
            const int s2 = (kc + 2) % 3;
            const __half* Ag = Ab + (kc + 2) * BK + (size_t)lrow * Kp + lcb * 8;
            const __half* Bg = Bb + (kc + 2) * BK + (size_t)lrow * Kp + lcb * 8;
            const uint32_t rowA = sbase + s2 * ASB + lrow * 128;
            const uint32_t rowB = rowA + BOFFB;
#pragma unroll
            for (int q = 0; q < 2; ++q) {
                const uint32_t sw = (uint32_t)(((lcb + q) ^ lxr) << 4);
                cp_async16(rowA + sw, Ag + q * 8);
                cp_async16(rowB + sw, Bg + q * 8);
            }
        }
        cp_commit();
    }

    cp_wait0();
    __syncthreads();

    float* sC = (float*)smem;                        // 64 x SDP fp32
    const int rr = lane >> 2;                        // 0..7
    const int cc0 = wn * 32 + (lane & 3) * 2;        // col base

    if (mode == 0) {
        // grp1 -> smem; grp0 adds and stores to global (register path)
        if (grp == 1) {
#pragma unroll
            for (int mt = 0; mt < 2; ++mt)
#pragma unroll
                for (int j = 0; j < 4; ++j) {
                    const int r0 = wm * 32 + rr + mt * 16;
                    const int c  = cc0 + j * 8;
                    float2 v0; v0.x = acc[mt][j][0]; v0.y = acc[mt][j][1];
                    float2 v1; v1.x = acc[mt][j][2]; v1.y = acc[mt][j][3];
                    *(float2*)(sC + r0 * SDP + c)       = v0;
                    *(float2*)(sC + (r0 + 8) * SDP + c) = v1;
                }
        }
        __syncthreads();
        if (grp == 0) {
            const int row0 = m0 + wm * 32 + rr;
            const int col0 = n0 + cc0;
#pragma unroll
            for (int mt = 0; mt < 2; ++mt) {
#pragma unroll
                for (int j = 0; j < 4; ++j) {
                    const int lr0 = wm * 32 + rr + mt * 16;
                    const int lc2 = cc0 + j * 8;
                    float2 p0 = *(float2*)(sC + lr0 * SDP + lc2);
                    float2 p1 = *(float2*)(sC + (lr0 + 8) * SDP + lc2);
                    const int col = col0 + j * 8;
                    const int r0 = row0 + mt * 16;
                    float* base = g_p1 + (size_t)bz * MTOT * HDIM;
                    float2 v0; v0.x = acc[mt][j][0] + p0.x; v0.y = acc[mt][j][1] + p0.y;
                    float2 v1; v1.x = acc[mt][j][2] + p1.x; v1.y = acc[mt][j][3] + p1.y;
                    *(float2*)(base + (size_t)r0 * HDIM + col)       = v0;
                    *(float2*)(base + (size_t)(r0 + 8) * HDIM + col) = v1;
                }
            }
        }
    } else {
        // materialize full tile in smem: grp1 stores, grp0 accumulates
        if (grp == 1) {
#pragma unroll
            for (int mt = 0; mt < 2; ++mt)
#pragma unroll
                for (int j = 0; j < 4; ++j) {
                    const int r0 = wm * 32 + rr + mt * 16;
                    const int c  = cc0 + j * 8;
                    float2 v0; v0.x = acc[mt][j][0]; v0.y = acc[mt][j][1];
                    float2 v1; v1.x = acc[mt][j][2]; v1.y = acc[mt][j][3];
                    *(float2*)(sC + r0 * SDP + c)       = v0;
                    *(float2*)(sC + (r0 + 8) * SDP + c) = v1;
                }
        }
        __syncthreads();
        if (grp == 0) {
#pragma unroll
            for (int mt = 0; mt < 2; ++mt)
#pragma unroll
                for (int j = 0; j < 4; ++j) {
                    const int r0 = wm * 32 + rr + mt * 16;
                    const int c  = cc0 + j * 8;
                    float2 p0 = *(float2*)(sC + r0 * SDP + c);
                    float2 p1 = *(float2*)(sC + (r0 + 8) * SDP + c);
                    p0.x += acc[mt][j][0]; p0.y += acc[mt][j][1];
                    p1.x += acc[mt][j][2]; p1.y += acc[mt][j][3];
                    *(float2*)(sC + r0 * SDP + c)       = p0;
                    *(float2*)(sC + (r0 + 8) * SDP + c) = p1;
                }
        }
        __syncthreads();

        const float bv0 = bias[0], bv1 = bias[1];
        // direct tile: rows i = m0 + r, cols jc = n0 + col
        {
            const int r  = tid >> 2;                 // 0..63
            const int cb = (tid & 3) * 16;           // 16 cols each
            float* dbase = outp + ((size_t)(bz * SEQ + m0 + r)) * NJC + n0;
#pragma unroll
            for (int e = 0; e < 8; ++e) {
                const int col = cb + e * 2;
                float2 v;
                v.x = sC[r * SDP + col] + bv0;
                v.y = sC[r * SDP + col + 1] + bv1;
                *(float2*)(dbase + col) = v;
            }
        }
        // mirror tile (off-diagonal pairs): out[b, j, 2*(m0+q)+c] = sC[q][2*jl+c]
        if (it != jt) {
            const int jl = tid >> 3;                 // 0..31
            const int ql = tid & 7;
            const int j  = jt * 64 + half * 32 + jl;
            float* mbase = outp + ((size_t)(bz * SEQ + j)) * NJC + 2 * m0;
#pragma unroll
            for (int e = 0; e < 8; ++e) {
                const int q = ql + 8 * e;
                float2 s = *(float2*)(sC + q * SDP + 2 * jl);
                float2 v;
                v.x = s.x + bv0;
                v.y = s.y + bv1;
                *(float2*)(mbase + 2 * q) = v;
            }
        }
    }
}

// ---------------------------------------------------------------------------
extern "C" void kernel_launch(void* const* d_in, const int* in_sizes, int n_in,
                              void* d_out, int out_size)
{
    const float* x  = (const float*)d_in[0];   // [4, 512, 1024]
    const float* W1 = (const float*)d_in[1];   // [256, 1024]
    const float* b1 = (const float*)d_in[2];   // [256]
    const float* W2 = (const float*)d_in[3];   // [2, 256]
    const float* b2 = (const float*)d_in[4];   // [2]
    float* out = (float*)d_out;                // [4, 512, 512, 2]

    // Prep 1: split inputs (fp16 2-term)
    split_xw<<<2304, 256>>>(x, W1);

    // Stage 1 GEMM (split-K=4): p1[z] = x @ W1^T over k-window z
    gemm_kernel<<<dim3(HDIM / BN, MTOT / BM, NSPLIT), 256, SMEM_SZ>>>(0, nullptr, nullptr);

    // Prep 2: fused reduce(+b1) + split + fold W2 into B operand
    prep_o<<<512, 256>>>(W2, b1);

    // Stage 2 GEMM (triangular): 36 pairs x 2 jc-halves x 4 batches = 288 CTAs
    gemm_kernel<<<dim3(2, 36, BNUM), 256, SMEM_SZ>>>(1, b2, out);
}

// round 12
// speedup vs baseline: 1.6316x; 1.0702x over previous
#include <cuda_runtime.h>
#include <cuda_fp16.h>
#include <cstdint>

#define BNUM   4
#define SEQ    512
#define DMODEL 1024
#define HDIM   256
#define MTOT   2048
#define KP1    1024      // stage-1 K (pure fp16, no split)
#define KP2    512       // 2 * HDIM (o_hi|o_lo concat)
#define NJC    1024      // SEQ * 2 (j,c interleaved)
#define NSPLIT 4         // split-K factor for stage-1 GEMM
#define KSPL   (KP1 / NSPLIT)   // 256 -> NC=4 per CTA

// Scratch (allocation-free __device__ globals)
__device__ __align__(16) float  g_p1[NSPLIT * MTOT * HDIM];  // 8 MB partials
__device__ __align__(16) __half g_Xp[MTOT * KP1];            // 4 MB
__device__ __align__(16) __half g_W1p[HDIM * KP1];           // 0.5 MB
__device__ __align__(16) __half g_Ap[MTOT * KP2];            // 2 MB
__device__ __align__(16) __half g_Bp[BNUM * NJC * KP2];      // 4 MB

// ---------------------------------------------------------------------------
// helpers
// ---------------------------------------------------------------------------
static __device__ __forceinline__ uint32_t smem_u32(const void* p) {
    uint32_t a;
    asm("{ .reg .u64 t; cvta.to.shared.u64 t, %1; cvt.u32.u64 %0, t; }"
        : "=r"(a) : "l"(p));
    return a;
}
static __device__ __forceinline__ void cp_async16(uint32_t saddr, const void* gaddr) {
    asm volatile("cp.async.cg.shared.global [%0], [%1], 16;"
                 :: "r"(saddr), "l"(gaddr) : "memory");
}
static __device__ __forceinline__ void cp_commit() {
    asm volatile("cp.async.commit_group;" ::: "memory");
}
static __device__ __forceinline__ void cp_wait1() {
    asm volatile("cp.async.wait_group 1;" ::: "memory");
}
static __device__ __forceinline__ void cp_wait0() {
    asm volatile("cp.async.wait_group 0;" ::: "memory");
}
static __device__ __forceinline__ void ldsm_x4(uint32_t* r, uint32_t addr) {
    asm volatile("ldmatrix.sync.aligned.m8n8.x4.shared.b16 {%0,%1,%2,%3}, [%4];"
                 : "=r"(r[0]), "=r"(r[1]), "=r"(r[2]), "=r"(r[3]) : "r"(addr));
}
static __device__ __forceinline__ void mma16816(float* d, const uint32_t* a,
                                                uint32_t b0, uint32_t b1) {
    asm volatile(
        "mma.sync.aligned.m16n8k16.row.col.f32.f16.f16.f32 "
        "{%0,%1,%2,%3}, {%4,%5,%6,%7}, {%8,%9}, {%0,%1,%2,%3};"
        : "+f"(d[0]), "+f"(d[1]), "+f"(d[2]), "+f"(d[3])
        : "r"(a[0]), "r"(a[1]), "r"(a[2]), "r"(a[3]), "r"(b0), "r"(b1));
}
static __device__ __forceinline__ void st_h2(__half* p, __half a, __half b) {
    __half2 t; t.x = a; t.y = b;
    *(__half2*)p = t;
}
static __device__ __forceinline__ void split1(float v, __half& h, __half& l) {
    h = __float2half_rn(v);
    l = __float2half_rn(v - __half2float(h));
}

// ---------------------------------------------------------------------------
// Prep 1: straight fp32 -> fp16 convert of X and W1 (no splitting)
// ---------------------------------------------------------------------------
__global__ __launch_bounds__(256) void split_xw(const float* __restrict__ X,
                                                const float* __restrict__ W1) {
    const int NX4 = MTOT * DMODEL / 4;   // 524288
    int idx = blockIdx.x * 256 + threadIdx.x;
    if (idx < NX4) {
        int r = idx >> 8;
        int k = (idx & 255) * 4;
        float4 v = *(const float4*)(X + (size_t)r * DMODEL + k);
        __half* base = g_Xp + (size_t)r * KP1 + k;
        st_h2(base,     __float2half_rn(v.x), __float2half_rn(v.y));
        st_h2(base + 2, __float2half_rn(v.z), __float2half_rn(v.w));
    } else {
        int i2 = idx - NX4;
        if (i2 >= HDIM * DMODEL / 4) return;
        int r = i2 >> 8;
        int k = (i2 & 255) * 4;
        float4 v = *(const float4*)(W1 + (size_t)r * DMODEL + k);
        __half* base = g_W1p + (size_t)r * KP1 + k;
        st_h2(base,     __float2half_rn(v.x), __float2half_rn(v.y));
        st_h2(base + 2, __float2half_rn(v.z), __float2half_rn(v.w));
    }
}

// ---------------------------------------------------------------------------
// Prep 2 (fused reduce): o = sum_s p1[s] + b1; A' = [o_hi | o_lo];
// B' rows jc=2j+c: v = o * w_c, [v_hi | v_hi]
// ---------------------------------------------------------------------------
__global__ __launch_bounds__(256) void prep_o(const float* __restrict__ W2,
                                              const float* __restrict__ b1) {
    int idx = blockIdx.x * 256 + threadIdx.x;       // over 2048*64
    int m = idx >> 6;
    int h = (idx & 63) * 4;

    float4 o4 = *(const float4*)(g_p1 + (size_t)m * HDIM + h);
#pragma unroll
    for (int s = 1; s < NSPLIT; ++s) {
        float4 p = *(const float4*)(g_p1 + ((size_t)s * MTOT + m) * HDIM + h);
        o4.x += p.x; o4.y += p.y; o4.z += p.z; o4.w += p.w;
    }
    float4 bb = *(const float4*)(b1 + h);
    o4.x += bb.x; o4.y += bb.y; o4.z += bb.z; o4.w += bb.w;

    __half h0,h1,h2,h3,l0,l1,l2,l3;
    split1(o4.x,h0,l0); split1(o4.y,h1,l1); split1(o4.z,h2,l2); split1(o4.w,h3,l3);
    __half* abase = g_Ap + (size_t)m * KP2 + h;
    st_h2(abase,        h0,h1); st_h2(abase+2,        h2,h3);
    st_h2(abase+HDIM,   l0,l1); st_h2(abase+HDIM+2,   l2,l3);

    int b = m >> 9, j = m & 511;
    float4 w0 = *(const float4*)(W2 + h);
    float4 w1 = *(const float4*)(W2 + HDIM + h);
#pragma unroll
    for (int c = 0; c < 2; ++c) {
        float4 w = c ? w1 : w0;
        __half v0 = __float2half_rn(o4.x * w.x);
        __half v1 = __float2half_rn(o4.y * w.y);
        __half v2 = __float2half_rn(o4.z * w.z);
        __half v3 = __float2half_rn(o4.w * w.w);
        __half* bbase = g_Bp + ((size_t)b * NJC + 2 * j + c) * KP2 + h;
        st_h2(bbase,        v0,v1); st_h2(bbase+2,        v2,v3);
        st_h2(bbase+HDIM,   v0,v1); st_h2(bbase+HDIM+2,   v2,v3);
    }
}

// ---------------------------------------------------------------------------
// mma.sync fp16 TN GEMM: D[64,64] = A[64,K] * B[64,K]^T, BK=64, 3-stage
// cp.async pipeline, 256 threads / 8 warps. Warps 0-3 consume ks 0-1 of each
// stage, warps 4-7 consume ks 2-3 (in-CTA K-split); combined via smem.
// mode 0: grid (4, 32, NSPLIT); C = g_p1[z] (k-window z*256..), NC=4
// mode 1: TRIANGULAR grid (2, 36, 4): blockIdx.y = pair (it<=jt) over 8x8
//   64-row blocks, blockIdx.x = jc half. NC=8; off-diagonal pairs also write
//   the mirrored tile out[b,j,i,c] from the smem-staged fp32 tile.
// ---------------------------------------------------------------------------
#define BM   64
#define BN   64
#define BK   64
#define ASB  8192                     // stage bytes (A or B): 64 rows * 128B
#define BOFFB (3 * ASB)               // B region offset: 24576
#define SMEM_SZ (6 * ASB)             // 49152 bytes == default 48KB limit
#define SDP  66                       // fp32 combine-tile pitch

__global__ __launch_bounds__(256, 4) void gemm_kernel(int mode,
                                                      const float* __restrict__ bias,
                                                      float* __restrict__ outp) {
    extern __shared__ char smem[];
    const uint32_t sbase = smem_u32(smem);
    const int tid = threadIdx.x;
    const int wid = tid >> 5, lane = tid & 31;
    const int grp = wid >> 2;                        // k-group 0/1
    const int wm = wid & 1, wn = (wid >> 1) & 1;     // 2x2 warp grid per group
    const int bz = blockIdx.z;

    int m0, n0, it = 0, jt = 0, half = 0;
    if (mode == 0) {
        m0 = blockIdx.y * BM;
        n0 = blockIdx.x * BN;
    } else {
        half = blockIdx.x;
        int p = blockIdx.y;                          // 0..35
        jt = 0;
        while (((jt + 1) * (jt + 2) >> 1) <= p) ++jt;
        it = p - ((jt * (jt + 1)) >> 1);
        m0 = it * 64;
        n0 = jt * 128 + half * 64;
    }

    const __half* Ab;
    const __half* Bb;
    int Kp, nc;
    if (mode == 0) { Ab = g_Xp + (size_t)m0 * KP1 + bz * KSPL;
                     Bb = g_W1p + (size_t)n0 * KP1 + bz * KSPL;
                     Kp = KP1; nc = KSPL / BK; }     // 4
    else           { Ab = g_Ap + ((size_t)(bz * SEQ + m0)) * KP2;
                     Bb = g_Bp + ((size_t)(bz * NJC + n0)) * KP2;
                     Kp = KP2; nc = KP2 / BK; }      // 8

    // per-thread load mapping: row = tid/4, 2x16B chunks starting at (tid&3)*32B
    const int lrow = tid >> 2;
    const int lcb  = (tid & 3) * 2;                  // first chunk index (16B units)
    const int lxr  = lrow & 7;                       // swizzle key

    float acc[2][4][4];
#pragma unroll
    for (int mt = 0; mt < 2; ++mt)
#pragma unroll
        for (int j = 0; j < 4; ++j)
#pragma unroll
            for (int e = 0; e < 4; ++e) acc[mt][j][e] = 0.0f;

    // prologue: stages 0,1
#pragma unroll
    for (int s = 0; s < 2; ++s) {
        const __half* Ag = Ab + s * BK + (size_t)lrow * Kp + lcb * 8;
        const __half* Bg = Bb + s * BK + (size_t)lrow * Kp + lcb * 8;
        const uint32_t rowA = sbase + s * ASB + lrow * 128;
        const uint32_t rowB = rowA + BOFFB;
#pragma unroll
        for (int q = 0; q < 2; ++q) {
            const uint32_t sw = (uint32_t)(((lcb + q) ^ lxr) << 4);
            cp_async16(rowA + sw, Ag + q * 8);
            cp_async16(rowB + sw, Bg + q * 8);
        }
        cp_commit();
    }

    // ldmatrix row bases; row+16 shares the same xor (16 % 8 == 0)
    const int arow = wm * 32 + (lane & 15);
    const int brow = wn * 32 + (lane & 15);
    const int kl   = lane >> 4;                      // 16B half within k16
    const uint32_t aRow = sbase + (uint32_t)(arow * 128);
    const uint32_t bRow = sbase + BOFFB + (uint32_t)(brow * 128);
    const int axr = arow & 7, bxr = brow & 7;

    for (int kc = 0; kc < nc; ++kc) {
        cp_wait1();
        __syncthreads();

        const int s = kc % 3;
        const uint32_t aS = aRow + (uint32_t)(s * ASB);
        const uint32_t bS = bRow + (uint32_t)(s * ASB);
#pragma unroll
        for (int ksi = 0; ksi < 2; ++ksi) {
            const int c16 = (grp * 2 + ksi) * 2 + kl;
            const uint32_t swa = (uint32_t)((c16 ^ axr) << 4);
            const uint32_t swb = (uint32_t)((c16 ^ bxr) << 4);
            uint32_t a0[4], a1[4], b0[4], b1[4];
            ldsm_x4(a0, aS + swa);
            ldsm_x4(a1, aS + 16 * 128 + swa);
            ldsm_x4(b0, bS + swb);
            ldsm_x4(b1, bS + 16 * 128 + swb);
            mma16816(acc[0][0], a0, b0[0], b0[2]);
            mma16816(acc[0][1], a0, b0[1], b0[3]);
            mma16816(acc[0][2], a0, b1[0], b1[2]);
            mma16816(acc[0][3], a0, b1[1], b1[3]);
            mma16816(acc[1][0], a1, b0[0], b0[2]);
            mma16816(acc[1][1], a1, b0[1], b0[3]);
            mma16816(acc[1][2], a1, b1[0], b1[2]);
            mma16816(acc[1][3], a1, b1[1], b1[3]);
        }

        if (kc + 2 < nc) {
            const int s2 = (kc + 2) % 3;
            const __half* Ag = Ab + (kc + 2) * BK + (size_t)lrow * Kp + lcb * 8;
            const __half* Bg = Bb + (kc + 2) * BK + (size_t)lrow * Kp + lcb * 8;
            const uint32_t rowA = sbase + s2 * ASB + lrow * 128;
            const uint32_t rowB = rowA + BOFFB;
#pragma unroll
            for (int q = 0; q < 2; ++q) {
                const uint32_t sw = (uint32_t)(((lcb + q) ^ lxr) << 4);
                cp_async16(rowA + sw, Ag + q * 8);
                cp_async16(rowB + sw, Bg + q * 8);
            }
        }
        cp_commit();
    }

    cp_wait0();
    __syncthreads();

    float* sC = (float*)smem;                        // 64 x SDP fp32
    const int rr = lane >> 2;                        // 0..7
    const int cc0 = wn * 32 + (lane & 3) * 2;        // col base

    if (mode == 0) {
        // grp1 -> smem; grp0 adds and stores to global (register path)
        if (grp == 1) {
#pragma unroll
            for (int mt = 0; mt < 2; ++mt)
#pragma unroll
                for (int j = 0; j < 4; ++j) {
                    const int r0 = wm * 32 + rr + mt * 16;
                    const int c  = cc0 + j * 8;
                    float2 v0; v0.x = acc[mt][j][0]; v0.y = acc[mt][j][1];
                    float2 v1; v1.x = acc[mt][j][2]; v1.y = acc[mt][j][3];
                    *(float2*)(sC + r0 * SDP + c)       = v0;
                    *(float2*)(sC + (r0 + 8) * SDP + c) = v1;
                }
        }
        __syncthreads();
        if (grp == 0) {
            const int row0 = m0 + wm * 32 + rr;
            const int col0 = n0 + cc0;
#pragma unroll
            for (int mt = 0; mt < 2; ++mt) {
#pragma unroll
                for (int j = 0; j < 4; ++j) {
                    const int lr0 = wm * 32 + rr + mt * 16;
                    const int lc2 = cc0 + j * 8;
                    float2 p0 = *(float2*)(sC + lr0 * SDP + lc2);
                    float2 p1 = *(float2*)(sC + (lr0 + 8) * SDP + lc2);
                    const int col = col0 + j * 8;
                    const int r0 = row0 + mt * 16;
                    float* base = g_p1 + (size_t)bz * MTOT * HDIM;
                    float2 v0; v0.x = acc[mt][j][0] + p0.x; v0.y = acc[mt][j][1] + p0.y;
                    float2 v1; v1.x = acc[mt][j][2] + p1.x; v1.y = acc[mt][j][3] + p1.y;
                    *(float2*)(base + (size_t)r0 * HDIM + col)       = v0;
                    *(float2*)(base + (size_t)(r0 + 8) * HDIM + col) = v1;
                }
            }
        }
    } else {
        // materialize full tile in smem: grp1 stores, grp0 accumulates
        if (grp == 1) {
#pragma unroll
            for (int mt = 0; mt < 2; ++mt)
#pragma unroll
                for (int j = 0; j < 4; ++j) {
                    const int r0 = wm * 32 + rr + mt * 16;
                    const int c  = cc0 + j * 8;
                    float2 v0; v0.x = acc[mt][j][0]; v0.y = acc[mt][j][1];
                    float2 v1; v1.x = acc[mt][j][2]; v1.y = acc[mt][j][3];
                    *(float2*)(sC + r0 * SDP + c)       = v0;
                    *(float2*)(sC + (r0 + 8) * SDP + c) = v1;
                }
        }
        __syncthreads();
        if (grp == 0) {
#pragma unroll
            for (int mt = 0; mt < 2; ++mt)
#pragma unroll
                for (int j = 0; j < 4; ++j) {
                    const int r0 = wm * 32 + rr + mt * 16;
                    const int c  = cc0 + j * 8;
                    float2 p0 = *(float2*)(sC + r0 * SDP + c);
                    float2 p1 = *(float2*)(sC + (r0 + 8) * SDP + c);
                    p0.x += acc[mt][j][0]; p0.y += acc[mt][j][1];
                    p1.x += acc[mt][j][2]; p1.y += acc[mt][j][3];
                    *(float2*)(sC + r0 * SDP + c)       = p0;
                    *(float2*)(sC + (r0 + 8) * SDP + c) = p1;
                }
        }
        __syncthreads();

        const float bv0 = bias[0], bv1 = bias[1];
        // direct tile: rows i = m0 + r, cols jc = n0 + col
        {
            const int r  = tid >> 2;                 // 0..63
            const int cb = (tid & 3) * 16;           // 16 cols each
            float* dbase = outp + ((size_t)(bz * SEQ + m0 + r)) * NJC + n0;
#pragma unroll
            for (int e = 0; e < 8; ++e) {
                const int col = cb + e * 2;
                float2 v;
                v.x = sC[r * SDP + col] + bv0;
                v.y = sC[r * SDP + col + 1] + bv1;
                *(float2*)(dbase + col) = v;
            }
        }
        // mirror tile (off-diagonal pairs): out[b, j, 2*(m0+q)+c] = sC[q][2*jl+c]
        if (it != jt) {
            const int jl = tid >> 3;                 // 0..31
            const int ql = tid & 7;
            const int j  = jt * 64 + half * 32 + jl;
            float* mbase = outp + ((size_t)(bz * SEQ + j)) * NJC + 2 * m0;
#pragma unroll
            for (int e = 0; e < 8; ++e) {
                const int q = ql + 8 * e;
                float2 s = *(float2*)(sC + q * SDP + 2 * jl);
                float2 v;
                v.x = s.x + bv0;
                v.y = s.y + bv1;
                *(float2*)(mbase + 2 * q) = v;
            }
        }
    }
}

// ---------------------------------------------------------------------------
extern "C" void kernel_launch(void* const* d_in, const int* in_sizes, int n_in,
                              void* d_out, int out_size)
{
    const float* x  = (const float*)d_in[0];   // [4, 512, 1024]
    const float* W1 = (const float*)d_in[1];   // [256, 1024]
    const float* b1 = (const float*)d_in[2];   // [256]
    const float* W2 = (const float*)d_in[3];   // [2, 256]
    const float* b2 = (const float*)d_in[4];   // [2]
    float* out = (float*)d_out;                // [4, 512, 512, 2]

    // Prep 1: fp32 -> fp16 convert
    split_xw<<<2304, 256>>>(x, W1);

    // Stage 1 GEMM (split-K=4): p1[z] = x @ W1^T over k-window z (NC=4)
    gemm_kernel<<<dim3(HDIM / BN, MTOT / BM, NSPLIT), 256, SMEM_SZ>>>(0, nullptr, nullptr);

    // Prep 2: fused reduce(+b1) + split + fold W2 into B operand
    prep_o<<<512, 256>>>(W2, b1);

    // Stage 2 GEMM (triangular): 36 pairs x 2 jc-halves x 4 batches = 288 CTAs
    gemm_kernel<<<dim3(2, 36, BNUM), 256, SMEM_SZ>>>(1, b2, out);
}

// round 13
// speedup vs baseline: 1.8980x; 1.1633x over previous
#include <cuda_runtime.h>
#include <cuda_fp16.h>
#include <cstdint>

#define BNUM   4
#define SEQ    512
#define DMODEL 1024
#define HDIM   256
#define MTOT   2048
#define KP1    1024      // stage-1 K (pure fp16)
#define KP2    256       // stage-2 K (pure fp16)
#define NJC    1024      // SEQ * 2 (j,c interleaved)
#define NSPLIT 4         // split-K factor for stage-1 GEMM
#define KSPL   (KP1 / NSPLIT)   // 256 -> NC=4 per CTA

// Scratch (allocation-free __device__ globals)
__device__ __align__(16) float  g_p1[NSPLIT * MTOT * HDIM];  // 8 MB partials
__device__ __align__(16) __half g_Xp[MTOT * KP1];            // 4 MB
__device__ __align__(16) __half g_W1p[HDIM * KP1];           // 0.5 MB
__device__ __align__(16) __half g_Ap[MTOT * KP2];            // 1 MB
__device__ __align__(16) __half g_Bp[BNUM * NJC * KP2];      // 2 MB

// ---------------------------------------------------------------------------
// helpers
// ---------------------------------------------------------------------------
static __device__ __forceinline__ uint32_t smem_u32(const void* p) {
    uint32_t a;
    asm("{ .reg .u64 t; cvta.to.shared.u64 t, %1; cvt.u32.u64 %0, t; }"
        : "=r"(a) : "l"(p));
    return a;
}
static __device__ __forceinline__ void cp_async16(uint32_t saddr, const void* gaddr) {
    asm volatile("cp.async.cg.shared.global [%0], [%1], 16;"
                 :: "r"(saddr), "l"(gaddr) : "memory");
}
static __device__ __forceinline__ void cp_commit() {
    asm volatile("cp.async.commit_group;" ::: "memory");
}
static __device__ __forceinline__ void cp_wait1() {
    asm volatile("cp.async.wait_group 1;" ::: "memory");
}
static __device__ __forceinline__ void cp_wait0() {
    asm volatile("cp.async.wait_group 0;" ::: "memory");
}
static __device__ __forceinline__ void ldsm_x4(uint32_t* r, uint32_t addr) {
    asm volatile("ldmatrix.sync.aligned.m8n8.x4.shared.b16 {%0,%1,%2,%3}, [%4];"
                 : "=r"(r[0]), "=r"(r[1]), "=r"(r[2]), "=r"(r[3]) : "r"(addr));
}
static __device__ __forceinline__ void mma16816(float* d, const uint32_t* a,
                                                uint32_t b0, uint32_t b1) {
    asm volatile(
        "mma.sync.aligned.m16n8k16.row.col.f32.f16.f16.f32 "
        "{%0,%1,%2,%3}, {%4,%5,%6,%7}, {%8,%9}, {%0,%1,%2,%3};"
        : "+f"(d[0]), "+f"(d[1]), "+f"(d[2]), "+f"(d[3])
        : "r"(a[0]), "r"(a[1]), "r"(a[2]), "r"(a[3]), "r"(b0), "r"(b1));
}
static __device__ __forceinline__ void st_h2(__half* p, __half a, __half b) {
    __half2 t; t.x = a; t.y = b;
    *(__half2*)p = t;
}

// ---------------------------------------------------------------------------
// Prep 1: straight fp32 -> fp16 convert of X and W1
// ---------------------------------------------------------------------------
__global__ __launch_bounds__(256) void split_xw(const float* __restrict__ X,
                                                const float* __restrict__ W1) {
    const int NX4 = MTOT * DMODEL / 4;   // 524288
    int idx = blockIdx.x * 256 + threadIdx.x;
    if (idx < NX4) {
        int r = idx >> 8;
        int k = (idx & 255) * 4;
        float4 v = *(const float4*)(X + (size_t)r * DMODEL + k);
        __half* base = g_Xp + (size_t)r * KP1 + k;
        st_h2(base,     __float2half_rn(v.x), __float2half_rn(v.y));
        st_h2(base + 2, __float2half_rn(v.z), __float2half_rn(v.w));
    } else {
        int i2 = idx - NX4;
        if (i2 >= HDIM * DMODEL / 4) return;
        int r = i2 >> 8;
        int k = (i2 & 255) * 4;
        float4 v = *(const float4*)(W1 + (size_t)r * DMODEL + k);
        __half* base = g_W1p + (size_t)r * KP1 + k;
        st_h2(base,     __float2half_rn(v.x), __float2half_rn(v.y));
        st_h2(base + 2, __float2half_rn(v.z), __float2half_rn(v.w));
    }
}

// ---------------------------------------------------------------------------
// Prep 2 (fused reduce): o = sum_s p1[s] + b1; A' = o (fp16);
// B' rows jc=2j+c: v = o * w_c (fp16)
// ---------------------------------------------------------------------------
__global__ __launch_bounds__(256) void prep_o(const float* __restrict__ W2,
                                              const float* __restrict__ b1) {
    int idx = blockIdx.x * 256 + threadIdx.x;       // over 2048*64
    int m = idx >> 6;
    int h = (idx & 63) * 4;

    float4 o4 = *(const float4*)(g_p1 + (size_t)m * HDIM + h);
#pragma unroll
    for (int s = 1; s < NSPLIT; ++s) {
        float4 p = *(const float4*)(g_p1 + ((size_t)s * MTOT + m) * HDIM + h);
        o4.x += p.x; o4.y += p.y; o4.z += p.z; o4.w += p.w;
    }
    float4 bb = *(const float4*)(b1 + h);
    o4.x += bb.x; o4.y += bb.y; o4.z += bb.z; o4.w += bb.w;

    __half* abase = g_Ap + (size_t)m * KP2 + h;
    st_h2(abase,     __float2half_rn(o4.x), __float2half_rn(o4.y));
    st_h2(abase + 2, __float2half_rn(o4.z), __float2half_rn(o4.w));

    int b = m >> 9, j = m & 511;
    float4 w0 = *(const float4*)(W2 + h);
    float4 w1 = *(const float4*)(W2 + HDIM + h);
#pragma unroll
    for (int c = 0; c < 2; ++c) {
        float4 w = c ? w1 : w0;
        __half* bbase = g_Bp + ((size_t)b * NJC + 2 * j + c) * KP2 + h;
        st_h2(bbase,     __float2half_rn(o4.x * w.x), __float2half_rn(o4.y * w.y));
        st_h2(bbase + 2, __float2half_rn(o4.z * w.z), __float2half_rn(o4.w * w.w));
    }
}

// ---------------------------------------------------------------------------
// mma.sync fp16 TN GEMM: D[64,64] = A[64,K] * B[64,K]^T, BK=64, 3-stage
// cp.async pipeline, 256 threads / 8 warps. Warps 0-3 consume ks 0-1 of each
// stage, warps 4-7 consume ks 2-3 (in-CTA K-split); combined via smem.
// mode 0: grid (4, 32, NSPLIT); C = g_p1[z] (k-window z*256..), NC=4
// mode 1: TRIANGULAR grid (2, 36, 4): blockIdx.y = pair (it<=jt) over 8x8
//   64-row blocks, blockIdx.x = jc half. NC=4; off-diagonal pairs also write
//   the mirrored tile out[b,j,i,c] from the smem-staged fp32 tile.
// ---------------------------------------------------------------------------
#define BM   64
#define BN   64
#define BK   64
#define ASB  8192                     // stage bytes (A or B): 64 rows * 128B
#define BOFFB (3 * ASB)               // B region offset: 24576
#define SMEM_SZ (6 * ASB)             // 49152 bytes == default 48KB limit
#define SDP  66                       // fp32 combine-tile pitch

__global__ __launch_bounds__(256, 4) void gemm_kernel(int mode,
                                                      const float* __restrict__ bias,
                                                      float* __restrict__ outp) {
    extern __shared__ char smem[];
    const uint32_t sbase = smem_u32(smem);
    const int tid = threadIdx.x;
    const int wid = tid >> 5, lane = tid & 31;
    const int grp = wid >> 2;                        // k-group 0/1
    const int wm = wid & 1, wn = (wid >> 1) & 1;     // 2x2 warp grid per group
    const int bz = blockIdx.z;

    int m0, n0, it = 0, jt = 0, half = 0;
    if (mode == 0) {
        m0 = blockIdx.y * BM;
        n0 = blockIdx.x * BN;
    } else {
        half = blockIdx.x;
        int p = blockIdx.y;                          // 0..35
        jt = 0;
        while (((jt + 1) * (jt + 2) >> 1) <= p) ++jt;
        it = p - ((jt * (jt + 1)) >> 1);
        m0 = it * 64;
        n0 = jt * 128 + half * 64;
    }

    const __half* Ab;
    const __half* Bb;
    int Kp, nc;
    if (mode == 0) { Ab = g_Xp + (size_t)m0 * KP1 + bz * KSPL;
                     Bb = g_W1p + (size_t)n0 * KP1 + bz * KSPL;
                     Kp = KP1; nc = KSPL / BK; }     // 4
    else           { Ab = g_Ap + ((size_t)(bz * SEQ + m0)) * KP2;
                     Bb = g_Bp + ((size_t)(bz * NJC + n0)) * KP2;
                     Kp = KP2; nc = KP2 / BK; }      // 4

    // per-thread load mapping: row = tid/4, 2x16B chunks starting at (tid&3)*32B
    const int lrow = tid >> 2;
    const int lcb  = (tid & 3) * 2;                  // first chunk index (16B units)
    const int lxr  = lrow & 7;                       // swizzle key

    float acc[2][4][4];
#pragma unroll
    for (int mt = 0; mt < 2; ++mt)
#pragma unroll
        for (int j = 0; j < 4; ++j)
#pragma unroll
            for (int e = 0; e < 4; ++e) acc[mt][j][e] = 0.0f;

    // prologue: stages 0,1
#pragma unroll
    for (int s = 0; s < 2; ++s) {
        const __half* Ag = Ab + s * BK + (size_t)lrow * Kp + lcb * 8;
        const __half* Bg = Bb + s * BK + (size_t)lrow * Kp + lcb * 8;
        const uint32_t rowA = sbase + s * ASB + lrow * 128;
        const uint32_t rowB = rowA + BOFFB;
#pragma unroll
        for (int q = 0; q < 2; ++q) {
            const uint32_t sw = (uint32_t)(((lcb + q) ^ lxr) << 4);
            cp_async16(rowA + sw, Ag + q * 8);
            cp_async16(rowB + sw, Bg + q * 8);
        }
        cp_commit();
    }

    // ldmatrix row bases; row+16 shares the same xor (16 % 8 == 0)
    const int arow = wm * 32 + (lane & 15);
    const int brow = wn * 32 + (lane & 15);
    const int kl   = lane >> 4;                      // 16B half within k16
    const uint32_t aRow = sbase + (uint32_t)(arow * 128);
    const uint32_t bRow = sbase + BOFFB + (uint32_t)(brow * 128);
    const int axr = arow & 7, bxr = brow & 7;

    for (int kc = 0; kc < nc; ++kc) {
        cp_wait1();
        __syncthreads();

        const int s = kc % 3;
        const uint32_t aS = aRow + (uint32_t)(s * ASB);
        const uint32_t bS = bRow + (uint32_t)(s * ASB);
#pragma unroll
        for (int ksi = 0; ksi < 2; ++ksi) {
            const int c16 = (grp * 2 + ksi) * 2 + kl;
            const uint32_t swa = (uint32_t)((c16 ^ axr) << 4);
            const uint32_t swb = (uint32_t)((c16 ^ bxr) << 4);
            uint32_t a0[4], a1[4], b0[4], b1[4];
            ldsm_x4(a0, aS + swa);
            ldsm_x4(a1, aS + 16 * 128 + swa);
            ldsm_x4(b0, bS + swb);
            ldsm_x4(b1, bS + 16 * 128 + swb);
            mma16816(acc[0][0], a0, b0[0], b0[2]);
            mma16816(acc[0][1], a0, b0[1], b0[3]);
            mma16816(acc[0][2], a0, b1[0], b1[2]);
            mma16816(acc[0][3], a0, b1[1], b1[3]);
            mma16816(acc[1][0], a1, b0[0], b0[2]);
            mma16816(acc[1][1], a1, b0[1], b0[3]);
            mma16816(acc[1][2], a1, b1[0], b1[2]);
            mma16816(acc[1][3], a1, b1[1], b1[3]);
        }

        if (kc + 2 < nc) {
            const int s2 = (kc + 2) % 3;
            const __half* Ag = Ab + (kc + 2) * BK + (size_t)lrow * Kp + lcb * 8;
            const __half* Bg = Bb + (kc + 2) * BK + (size_t)lrow * Kp + lcb * 8;
            const uint32_t rowA = sbase + s2 * ASB + lrow * 128;
            const uint32_t rowB = rowA + BOFFB;
#pragma unroll
            for (int q = 0; q < 2; ++q) {
                const uint32_t sw = (uint32_t)(((lcb + q) ^ lxr) << 4);
                cp_async16(rowA + sw, Ag + q * 8);
                cp_async16(rowB + sw, Bg + q * 8);
            }
        }
        cp_commit();
    }

    cp_wait0();
    __syncthreads();

    float* sC = (float*)smem;                        // 64 x SDP fp32
    const int rr = lane >> 2;                        // 0..7
    const int cc0 = wn * 32 + (lane & 3) * 2;        // col base

    if (mode == 0) {
        // grp1 -> smem; grp0 adds and stores to global (register path)
        if (grp == 1) {
#pragma unroll
            for (int mt = 0; mt < 2; ++mt)
#pragma unroll
                for (int j = 0; j < 4; ++j) {
                    const int r0 = wm * 32 + rr + mt * 16;
                    const int c  = cc0 + j * 8;
                    float2 v0; v0.x = acc[mt][j][0]; v0.y = acc[mt][j][1];
                    float2 v1; v1.x = acc[mt][j][2]; v1.y = acc[mt][j][3];
                    *(float2*)(sC + r0 * SDP + c)       = v0;
                    *(float2*)(sC + (r0 + 8) * SDP + c) = v1;
                }
        }
        __syncthreads();
        if (grp == 0) {
            const int row0 = m0 + wm * 32 + rr;
            const int col0 = n0 + cc0;
#pragma unroll
            for (int mt = 0; mt < 2; ++mt) {
#pragma unroll
                for (int j = 0; j < 4; ++j) {
                    const int lr0 = wm * 32 + rr + mt * 16;
                    const int lc2 = cc0 + j * 8;
                    float2 p0 = *(float2*)(sC + lr0 * SDP + lc2);
                    float2 p1 = *(float2*)(sC + (lr0 + 8) * SDP + lc2);
                    const int col = col0 + j * 8;
                    const int r0 = row0 + mt * 16;
                    float* base = g_p1 + (size_t)bz * MTOT * HDIM;
                    float2 v0; v0.x = acc[mt][j][0] + p0.x; v0.y = acc[mt][j][1] + p0.y;
                    float2 v1; v1.x = acc[mt][j][2] + p1.x; v1.y = acc[mt][j][3] + p1.y;
                    *(float2*)(base + (size_t)r0 * HDIM + col)       = v0;
                    *(float2*)(base + (size_t)(r0 + 8) * HDIM + col) = v1;
                }
            }
        }
    } else {
        // materialize full tile in smem: grp1 stores, grp0 accumulates
        if (grp == 1) {
#pragma unroll
            for (int mt = 0; mt < 2; ++mt)
#pragma unroll
                for (int j = 0; j < 4; ++j) {
                    const int r0 = wm * 32 + rr + mt * 16;
                    const int c  = cc0 + j * 8;
                    float2 v0; v0.x = acc[mt][j][0]; v0.y = acc[mt][j][1];
                    float2 v1; v1.x = acc[mt][j][2]; v1.y = acc[mt][j][3];
                    *(float2*)(sC + r0 * SDP + c)       = v0;
                    *(float2*)(sC + (r0 + 8) * SDP + c) = v1;
                }
        }
        __syncthreads();
        if (grp == 0) {
#pragma unroll
            for (int mt = 0; mt < 2; ++mt)
#pragma unroll
                for (int j = 0; j < 4; ++j) {
                    const int r0 = wm * 32 + rr + mt * 16;
                    const int c  = cc0 + j * 8;
                    float2 p0 = *(float2*)(sC + r0 * SDP + c);
                    float2 p1 = *(float2*)(sC + (r0 + 8) * SDP + c);
                    p0.x += acc[mt][j][0]; p0.y += acc[mt][j][1];
                    p1.x += acc[mt][j][2]; p1.y += acc[mt][j][3];
                    *(float2*)(sC + r0 * SDP + c)       = p0;
                    *(float2*)(sC + (r0 + 8) * SDP + c) = p1;
                }
        }
        __syncthreads();

        const float bv0 = bias[0], bv1 = bias[1];
        // direct tile: rows i = m0 + r, cols jc = n0 + col
        {
            const int r  = tid >> 2;                 // 0..63
            const int cb = (tid & 3) * 16;           // 16 cols each
            float* dbase = outp + ((size_t)(bz * SEQ + m0 + r)) * NJC + n0;
#pragma unroll
            for (int e = 0; e < 8; ++e) {
                const int col = cb + e * 2;
                float2 v;
                v.x = sC[r * SDP + col] + bv0;
                v.y = sC[r * SDP + col + 1] + bv1;
                *(float2*)(dbase + col) = v;
            }
        }
        // mirror tile (off-diagonal pairs): out[b, j, 2*(m0+q)+c] = sC[q][2*jl+c]
        if (it != jt) {
            const int jl = tid >> 3;                 // 0..31
            const int ql = tid & 7;
            const int j  = jt * 64 + half * 32 + jl;
            float* mbase = outp + ((size_t)(bz * SEQ + j)) * NJC + 2 * m0;
#pragma unroll
            for (int e = 0; e < 8; ++e) {
                const int q = ql + 8 * e;
                float2 s = *(float2*)(sC + q * SDP + 2 * jl);
                float2 v;
                v.x = s.x + bv0;
                v.y = s.y + bv1;
                *(float2*)(mbase + 2 * q) = v;
            }
        }
    }
}

// ---------------------------------------------------------------------------
extern "C" void kernel_launch(void* const* d_in, const int* in_sizes, int n_in,
                              void* d_out, int out_size)
{
    const float* x  = (const float*)d_in[0];   // [4, 512, 1024]
    const float* W1 = (const float*)d_in[1];   // [256, 1024]
    const float* b1 = (const float*)d_in[2];   // [256]
    const float* W2 = (const float*)d_in[3];   // [2, 256]
    const float* b2 = (const float*)d_in[4];   // [2]
    float* out = (float*)d_out;                // [4, 512, 512, 2]

    // Prep 1: fp32 -> fp16 convert
    split_xw<<<2304, 256>>>(x, W1);

    // Stage 1 GEMM (split-K=4): p1[z] = x @ W1^T over k-window z (NC=4)
    gemm_kernel<<<dim3(HDIM / BN, MTOT / BM, NSPLIT), 256, SMEM_SZ>>>(0, nullptr, nullptr);

    // Prep 2: fused reduce(+b1) + convert + fold W2 into B operand
    prep_o<<<512, 256>>>(W2, b1);

    // Stage 2 GEMM (triangular): 36 pairs x 2 jc-halves x 4 batches = 288 CTAs
    gemm_kernel<<<dim3(2, 36, BNUM), 256, SMEM_SZ>>>(1, b2, out);
}